// round 1
// baseline (speedup 1.0000x reference)
#include <cuda_runtime.h>
#include <math.h>

#define BATCH 4
#define SEQ   1024
#define DM    1024
#define NH    16
#define HD    64
#define TOK   (BATCH*SEQ)   // 4096
#define BH    (BATCH*NH)    // 64
#define DFF   4096

// ---------------- scratch (device globals; no allocation allowed) -----------
__device__ float g_lx [(size_t)TOK*DM];
__device__ float g_q  [(size_t)TOK*DM];
__device__ float g_k  [(size_t)TOK*DM];
__device__ float g_v  [(size_t)TOK*DM];
__device__ float g_qt [BH*SEQ];
__device__ float g_kt [BH*SEQ];
__device__ float g_vt [BH*SEQ];
__device__ float g_S  [(size_t)BH*SEQ*SEQ];     // 256 MB scores
__device__ float g_cat[(size_t)TOK*1040];
__device__ float g_ax [(size_t)TOK*1023];
__device__ float g_x2 [(size_t)TOK*DM];
__device__ float g_h1 [(size_t)TOK*DM];
__device__ float g_hf [(size_t)TOK*DFF];
__device__ float g_pj [(size_t)TOK*1023];

// ---------------- block reductions ------------------------------------------
__device__ __forceinline__ float block_sum(float v, float* sm) {
    int lane = threadIdx.x & 31, wid = threadIdx.x >> 5;
#pragma unroll
    for (int o = 16; o; o >>= 1) v += __shfl_down_sync(0xffffffffu, v, o);
    if (lane == 0) sm[wid] = v;
    __syncthreads();
    if (wid == 0) {
        float r = (lane < ((blockDim.x + 31) >> 5)) ? sm[lane] : 0.f;
#pragma unroll
        for (int o = 16; o; o >>= 1) r += __shfl_down_sync(0xffffffffu, r, o);
        if (lane == 0) sm[0] = r;
    }
    __syncthreads();
    float r = sm[0];
    __syncthreads();
    return r;
}

__device__ __forceinline__ float block_max(float v, float* sm) {
    int lane = threadIdx.x & 31, wid = threadIdx.x >> 5;
#pragma unroll
    for (int o = 16; o; o >>= 1) v = fmaxf(v, __shfl_down_sync(0xffffffffu, v, o));
    if (lane == 0) sm[wid] = v;
    __syncthreads();
    if (wid == 0) {
        float r = (lane < ((blockDim.x + 31) >> 5)) ? sm[lane] : -1e30f;
#pragma unroll
        for (int o = 16; o; o >>= 1) r = fmaxf(r, __shfl_down_sync(0xffffffffu, r, o));
        if (lane == 0) sm[0] = r;
    }
    __syncthreads();
    float r = sm[0];
    __syncthreads();
    return r;
}

// ---------------- generic tiled SGEMM: C = A(MxK) @ B(KxN) + bias -----------
// K must be a multiple of 8 and M a multiple of 128 (true for all calls).
__global__ __launch_bounds__(256)
void sgemm_bias(const float* __restrict__ A, const float* __restrict__ Bm,
                const float* __restrict__ bias, float* __restrict__ C,
                int M, int N, int K, int ldc, int coff) {
    __shared__ float As[8][128];
    __shared__ float Bs[8][128];
    int tid  = threadIdx.x;
    int row0 = blockIdx.y * 128, col0 = blockIdx.x * 128;
    int tr = tid >> 4, tc = tid & 15;
    int aRow = tid >> 1, aCol = (tid & 1) * 4;
    int bRow = tid >> 5, bCol = (tid & 31) * 4;
    float acc[8][8];
#pragma unroll
    for (int i = 0; i < 8; i++)
#pragma unroll
        for (int j = 0; j < 8; j++) acc[i][j] = 0.f;

    for (int k0 = 0; k0 < K; k0 += 8) {
        float4 av = *reinterpret_cast<const float4*>(A + (size_t)(row0 + aRow) * K + k0 + aCol);
        As[aCol + 0][aRow] = av.x; As[aCol + 1][aRow] = av.y;
        As[aCol + 2][aRow] = av.z; As[aCol + 3][aRow] = av.w;
#pragma unroll
        for (int j = 0; j < 4; j++) {
            int c = col0 + bCol + j;
            Bs[bRow][bCol + j] = (c < N) ? Bm[(size_t)(k0 + bRow) * N + c] : 0.f;
        }
        __syncthreads();
#pragma unroll
        for (int k = 0; k < 8; k++) {
            float a[8], b[8];
            float4 a0 = *reinterpret_cast<const float4*>(&As[k][tr * 8]);
            float4 a1 = *reinterpret_cast<const float4*>(&As[k][tr * 8 + 4]);
            float4 b0 = *reinterpret_cast<const float4*>(&Bs[k][tc * 8]);
            float4 b1 = *reinterpret_cast<const float4*>(&Bs[k][tc * 8 + 4]);
            a[0]=a0.x;a[1]=a0.y;a[2]=a0.z;a[3]=a0.w;a[4]=a1.x;a[5]=a1.y;a[6]=a1.z;a[7]=a1.w;
            b[0]=b0.x;b[1]=b0.y;b[2]=b0.z;b[3]=b0.w;b[4]=b1.x;b[5]=b1.y;b[6]=b1.z;b[7]=b1.w;
#pragma unroll
            for (int i = 0; i < 8; i++)
#pragma unroll
                for (int j = 0; j < 8; j++) acc[i][j] += a[i] * b[j];
        }
        __syncthreads();
    }
#pragma unroll
    for (int i = 0; i < 8; i++) {
        int r = row0 + tr * 8 + i;
#pragma unroll
        for (int j = 0; j < 8; j++) {
            int c = col0 + tc * 8 + j;
            if (c < N) C[(size_t)r * ldc + coff + c] = acc[i][j] + bias[c];
        }
    }
}

// ---------------- Lorentz layernorm + lift ----------------------------------
__global__ __launch_bounds__(256)
void lnorm_kernel(const float* __restrict__ xin, const float* __restrict__ g,
                  const float* __restrict__ be, float* __restrict__ out) {
    __shared__ float sm[32];
    int t = blockIdx.x, tid = threadIdx.x;
    const float* xr = xin + (size_t)t * DM + 1;   // space part (1023)
    float v[4]; float s = 0.f;
#pragma unroll
    for (int j = 0; j < 4; j++) {
        int d = tid + j * 256;
        if (d < 1023) { v[j] = xr[d]; s += v[j]; } else v[j] = 0.f;
    }
    s = block_sum(s, sm);
    float mu = s * (1.f / 1023.f);
    float vs = 0.f;
#pragma unroll
    for (int j = 0; j < 4; j++) {
        int d = tid + j * 256;
        if (d < 1023) { float dd = v[j] - mu; vs += dd * dd; }
    }
    vs = block_sum(vs, sm);
    float inv = rsqrtf(vs * (1.f / 1023.f) + 1e-5f);
    float tt = 0.f;
#pragma unroll
    for (int j = 0; j < 4; j++) {
        int d = tid + j * 256;
        if (d < 1023) {
            float y = (v[j] - mu) * inv * g[d] + be[d];
            tt += y * y;
            out[(size_t)t * DM + 1 + d] = y;
        }
    }
    tt = block_sum(tt, sm);
    if (tid == 0) out[(size_t)t * DM] = sqrtf(tt + 1.f);
}

// ---------------- per-head time lift for q,k,v ------------------------------
__global__ __launch_bounds__(512)
void qkv_times() {
    int t = blockIdx.x;               // token
    int b = t >> 10, n = t & 1023;
    int h = threadIdx.x >> 5;         // head = warp
    int lane = threadIdx.x & 31;
    const float* rows[3] = { g_q + (size_t)t * DM, g_k + (size_t)t * DM, g_v + (size_t)t * DM };
    float* outs[3] = { g_qt, g_kt, g_vt };
#pragma unroll
    for (int a = 0; a < 3; a++) {
        float v0 = rows[a][h * 64 + lane], v1 = rows[a][h * 64 + 32 + lane];
        float s = v0 * v0 + v1 * v1;
#pragma unroll
        for (int o = 16; o; o >>= 1) s += __shfl_down_sync(0xffffffffu, s, o);
        if (lane == 0) outs[a][((b * NH + h) << 10) + n] = sqrtf(s + 1.0f);
    }
}

// ---------------- attention scores ((2 + 2*minkowski)/8) --------------------
__global__ __launch_bounds__(256)
void attn_scores() {
    int bh = blockIdx.z;
    int b = bh >> 4, h = bh & 15;
    int q0 = blockIdx.y * 64, k0 = blockIdx.x * 64;
    __shared__ float Qs[64][65];   // [d][row]
    __shared__ float Ks[64][65];
    int tid = threadIdx.x;
    int d = tid & 63, r4 = tid >> 6;
    size_t baseq = ((size_t)(b * SEQ + q0)) * DM + h * 64;
    size_t basek = ((size_t)(b * SEQ + k0)) * DM + h * 64;
    for (int r = r4; r < 64; r += 4) {
        Qs[d][r] = g_q[baseq + (size_t)r * DM + d];
        Ks[d][r] = g_k[basek + (size_t)r * DM + d];
    }
    __syncthreads();
    int tr = tid >> 4, tc = tid & 15;
    float acc[4][4];
#pragma unroll
    for (int i = 0; i < 4; i++)
#pragma unroll
        for (int j = 0; j < 4; j++) acc[i][j] = 0.f;
#pragma unroll 8
    for (int dd = 0; dd < 64; dd++) {
        float a[4], bb[4];
#pragma unroll
        for (int i = 0; i < 4; i++) a[i]  = Qs[dd][tr * 4 + i];
#pragma unroll
        for (int j = 0; j < 4; j++) bb[j] = Ks[dd][tc * 4 + j];
#pragma unroll
        for (int i = 0; i < 4; i++)
#pragma unroll
            for (int j = 0; j < 4; j++) acc[i][j] += a[i] * bb[j];
    }
    float qtv[4], ktv[4];
#pragma unroll
    for (int i = 0; i < 4; i++) qtv[i] = g_qt[(bh << 10) + q0 + tr * 4 + i];
#pragma unroll
    for (int j = 0; j < 4; j++) ktv[j] = g_kt[(bh << 10) + k0 + tc * 4 + j];
#pragma unroll
    for (int i = 0; i < 4; i++) {
        size_t rowo = ((size_t)(bh << 10) + q0 + tr * 4 + i) * SEQ + k0 + tc * 4;
#pragma unroll
        for (int j = 0; j < 4; j++)
            g_S[rowo + j] = 0.25f + 0.25f * (acc[i][j] - qtv[i] * ktv[j]);
    }
}

// ---------------- row softmax ------------------------------------------------
__global__ __launch_bounds__(256)
void softmax_rows() {
    __shared__ float sm[32];
    size_t row = blockIdx.x;
    float* p = g_S + row * SEQ;
    int tid = threadIdx.x;
    float v[4], mx = -1e30f;
#pragma unroll
    for (int j = 0; j < 4; j++) { v[j] = p[tid + j * 256]; mx = fmaxf(mx, v[j]); }
    mx = block_max(mx, sm);
    float s = 0.f;
#pragma unroll
    for (int j = 0; j < 4; j++) { v[j] = __expf(v[j] - mx); s += v[j]; }
    s = block_sum(s, sm);
    float inv = 1.f / s;
#pragma unroll
    for (int j = 0; j < 4; j++) p[tid + j * 256] = v[j] * inv;
}

// ---------------- PV + Minkowski normalize + scatter to cat -----------------
__global__ __launch_bounds__(256)
void attn_pv() {
    int bh = blockIdx.y;
    int b = bh >> 4, h = bh & 15;
    int q0 = blockIdx.x * 64;
    __shared__ float At[64][65];   // [q][k]
    __shared__ float Vt[64][72];   // [k][c] c=0 time, 1..64 space, 65..71 zero pad
    int tid = threadIdx.x;
    int rg = tid >> 3;             // 0..31 -> queries 2rg,2rg+1
    int p  = tid & 7;              // col group
    int c0 = p * 9;
    int nc = (65 - c0 < 9) ? (65 - c0) : 9;
    float acc0[9], acc1[9];
#pragma unroll
    for (int c = 0; c < 9; c++) { acc0[c] = 0.f; acc1[c] = 0.f; }

    int kk = tid & 63, qr = tid >> 6;
    if (tid < 64) {
#pragma unroll
        for (int c = 65; c < 72; c++) Vt[tid][c] = 0.f;
    }
    for (int k0 = 0; k0 < SEQ; k0 += 64) {
        for (int r = qr; r < 64; r += 4) {
            At[r][kk]     = g_S[((size_t)(bh << 10) + q0 + r) * SEQ + k0 + kk];
            Vt[r][1 + kk] = g_v[((size_t)(b * SEQ + k0 + r)) * DM + h * 64 + kk];
        }
        if (tid < 64) Vt[tid][0] = g_vt[(bh << 10) + k0 + tid];
        __syncthreads();
#pragma unroll 4
        for (int k = 0; k < 64; k++) {
            float a0 = At[2 * rg][k], a1 = At[2 * rg + 1][k];
#pragma unroll
            for (int c = 0; c < 9; c++) {
                float vv = Vt[k][c0 + c];
                acc0[c] += a0 * vv;
                acc1[c] += a1 * vv;
            }
        }
        __syncthreads();
    }
    // minkowski inner = sum(space^2) - time^2 ; reduce over the 8 col-threads
    float lin0 = 0.f, lin1 = 0.f;
#pragma unroll
    for (int c = 0; c < 9; c++) {
        if (c < nc) {
            float s0 = acc0[c] * acc0[c], s1 = acc1[c] * acc1[c];
            if (c0 + c == 0) { lin0 -= s0; lin1 -= s1; }
            else             { lin0 += s0; lin1 += s1; }
        }
    }
#pragma unroll
    for (int o = 4; o; o >>= 1) {
        lin0 += __shfl_down_sync(0xffffffffu, lin0, o, 8);
        lin1 += __shfl_down_sync(0xffffffffu, lin1, o, 8);
    }
    lin0 = __shfl_sync(0xffffffffu, lin0, 0, 8);
    lin1 = __shfl_sync(0xffffffffu, lin1, 0, 8);
    float inv0 = rsqrtf(fmaxf(-lin0, 1e-8f));
    float inv1 = rsqrtf(fmaxf(-lin1, 1e-8f));
    size_t o0 = ((size_t)(b * SEQ + q0 + 2 * rg))     * 1040 + h * 65 + c0;
    size_t o1 = ((size_t)(b * SEQ + q0 + 2 * rg + 1)) * 1040 + h * 65 + c0;
#pragma unroll
    for (int c = 0; c < 9; c++) {
        if (c < nc) {
            g_cat[o0 + c] = acc0[c] * inv0;
            g_cat[o1 + c] = acc1[c] * inv1;
        }
    }
}

// ---------------- Lorentz resnet: out = normalize(x + w*lift(y_space)) ------
__global__ __launch_bounds__(256)
void lresnet_kernel(const float* __restrict__ xin, const float* __restrict__ ysp,
                    const float* __restrict__ wp, float* __restrict__ out) {
    __shared__ float sm[32];
    int t = blockIdx.x, tid = threadIdx.x;
    const float* xr = xin + (size_t)t * DM;
    const float* yr = ysp + (size_t)t * 1023;
    float yv[4]; float ss = 0.f;
#pragma unroll
    for (int j = 0; j < 4; j++) {
        int d = tid + j * 256;
        if (d >= 1) { yv[j] = yr[d - 1]; ss += yv[j] * yv[j]; } else yv[j] = 0.f;
    }
    ss = block_sum(ss, sm);
    float w0 = *wp;
    float ytime = sqrtf(ss + 1.0f);
    float z[4]; float lin = 0.f;
#pragma unroll
    for (int j = 0; j < 4; j++) {
        int d = tid + j * 256;
        float y = (d == 0) ? ytime : yv[j];
        z[j] = xr[d] + w0 * y;
        lin += (d == 0) ? -z[j] * z[j] : z[j] * z[j];
    }
    lin = block_sum(lin, sm);
    float inv = rsqrtf(fmaxf(-lin, 1e-8f));
#pragma unroll
    for (int j = 0; j < 4; j++)
        out[(size_t)t * DM + tid + j * 256] = z[j] * inv;
}

// ---------------- exact GELU on space dims + time lift into col 0 -----------
__global__ __launch_bounds__(256)
void gelu_time() {
    __shared__ float sm[32];
    int t = blockIdx.x, tid = threadIdx.x;
    float* r = g_hf + (size_t)t * DFF;
    float vals[16]; float s = 0.f;
#pragma unroll
    for (int j = 0; j < 16; j++) {
        int d = 1 + tid + j * 256;
        if (d < DFF) {
            float x = r[d];
            float gg = x * normcdff(x);
            vals[j] = gg;
            s += gg * gg;
        } else vals[j] = 0.f;
    }
    s = block_sum(s, sm);
#pragma unroll
    for (int j = 0; j < 16; j++) {
        int d = 1 + tid + j * 256;
        if (d < DFF) r[d] = vals[j];
    }
    if (tid == 0) r[0] = sqrtf(s + 1.f);
}

// ---------------- launch ------------------------------------------------------
extern "C" void kernel_launch(void* const* d_in, const int* in_sizes, int n_in,
                              void* d_out, int out_size) {
    const float* x   = (const float*)d_in[0];
    const float* g1  = (const float*)d_in[1];
    const float* b1  = (const float*)d_in[2];
    const float* Wq  = (const float*)d_in[3];
    const float* bq  = (const float*)d_in[4];
    const float* Wk  = (const float*)d_in[5];
    const float* bk  = (const float*)d_in[6];
    const float* Wv  = (const float*)d_in[7];
    const float* bv  = (const float*)d_in[8];
    const float* Wo  = (const float*)d_in[9];
    const float* bo  = (const float*)d_in[10];
    const float* g2  = (const float*)d_in[11];
    const float* b2  = (const float*)d_in[12];
    const float* Wfc = (const float*)d_in[13];
    const float* bfc = (const float*)d_in[14];
    const float* Wpj = (const float*)d_in[15];
    const float* bpj = (const float*)d_in[16];
    const float* w1  = (const float*)d_in[17];
    const float* w2  = (const float*)d_in[18];
    float* out = (float*)d_out;

    float *p_lx, *p_q, *p_k, *p_v, *p_cat, *p_ax, *p_x2, *p_h1, *p_hf, *p_pj;
    cudaGetSymbolAddress((void**)&p_lx,  g_lx);
    cudaGetSymbolAddress((void**)&p_q,   g_q);
    cudaGetSymbolAddress((void**)&p_k,   g_k);
    cudaGetSymbolAddress((void**)&p_v,   g_v);
    cudaGetSymbolAddress((void**)&p_cat, g_cat);
    cudaGetSymbolAddress((void**)&p_ax,  g_ax);
    cudaGetSymbolAddress((void**)&p_x2,  g_x2);
    cudaGetSymbolAddress((void**)&p_h1,  g_h1);
    cudaGetSymbolAddress((void**)&p_hf,  g_hf);
    cudaGetSymbolAddress((void**)&p_pj,  g_pj);

    // 1. lx = lorentz_layernorm(x)
    lnorm_kernel<<<TOK, 256>>>(x, g1, b1, p_lx);
    // 2. QKV projections
    sgemm_bias<<<dim3(8, 32), 256>>>(p_lx, Wq, bq, p_q, TOK, 1024, 1024, 1024, 0);
    sgemm_bias<<<dim3(8, 32), 256>>>(p_lx, Wk, bk, p_k, TOK, 1024, 1024, 1024, 0);
    sgemm_bias<<<dim3(8, 32), 256>>>(p_lx, Wv, bv, p_v, TOK, 1024, 1024, 1024, 0);
    // 3. per-head time lifts
    qkv_times<<<TOK, 512>>>();
    // 4. scores, softmax, PV(+normalize, scatter to cat)
    attn_scores<<<dim3(16, 16, BH), 256>>>();
    softmax_rows<<<BH * SEQ, 256>>>();
    attn_pv<<<dim3(16, BH), 256>>>();
    // 5. output projection + first lorentz resnet
    sgemm_bias<<<dim3(8, 32), 256>>>(p_cat, Wo, bo, p_ax, TOK, 1023, 1040, 1023, 0);
    lresnet_kernel<<<TOK, 256>>>(x, p_ax, w1, p_x2);
    // 6. MLP branch
    lnorm_kernel<<<TOK, 256>>>(p_x2, g2, b2, p_h1);
    sgemm_bias<<<dim3(32, 32), 256>>>(p_h1, Wfc, bfc, p_hf, TOK, 4095, 1024, DFF, 1);
    gelu_time<<<TOK, 256>>>();
    sgemm_bias<<<dim3(8, 32), 256>>>(p_hf, Wpj, bpj, p_pj, TOK, 1023, DFF, 1023, 0);
    // 7. final lorentz resnet -> output
    lresnet_kernel<<<TOK, 256>>>(p_x2, p_pj, w2, out);
}

// round 3
// speedup vs baseline: 1.7995x; 1.7995x over previous
#include <cuda_runtime.h>
#include <cuda_bf16.h>
#include <math.h>
#include <stdint.h>

#define BATCH 4
#define SEQ   1024
#define DM    1024
#define NH    16
#define HD    64
#define TOK   (BATCH*SEQ)   // 4096
#define BH    (BATCH*NH)    // 64
#define DFF   4096

typedef __nv_bfloat16 bf16;

// ---------------- scratch (device globals; no allocation allowed) -----------
__device__ bf16  g_lxh[(size_t)TOK*DM];
__device__ bf16  g_lxl[(size_t)TOK*DM];
__device__ float g_q  [(size_t)TOK*DM];
__device__ float g_k  [(size_t)TOK*DM];
__device__ float g_v  [(size_t)TOK*DM];
__device__ float g_qt [BH*SEQ];
__device__ float g_kt [BH*SEQ];
__device__ float g_vt [BH*SEQ];
__device__ float g_S  [(size_t)BH*SEQ*SEQ];     // 256 MB scores
__device__ bf16  g_cath[(size_t)TOK*1088];      // padded K for Wo gemm (zeros in pad)
__device__ bf16  g_catl[(size_t)TOK*1088];
__device__ float g_ax [(size_t)TOK*1023];
__device__ float g_x2 [(size_t)TOK*DM];
__device__ bf16  g_h1h[(size_t)TOK*DM];
__device__ bf16  g_h1l[(size_t)TOK*DM];
__device__ float g_hf [(size_t)TOK*DFF];
__device__ bf16  g_hfh[(size_t)TOK*DFF];
__device__ bf16  g_hfl[(size_t)TOK*DFF];
__device__ float g_pj [(size_t)TOK*1023];
// transposed/split weights: [Npad][Kpad] K-major bf16 (pads stay zero-init)
__device__ bf16 g_WqTh[(size_t)1024*1024];  __device__ bf16 g_WqTl[(size_t)1024*1024];
__device__ bf16 g_WkTh[(size_t)1024*1024];  __device__ bf16 g_WkTl[(size_t)1024*1024];
__device__ bf16 g_WvTh[(size_t)1024*1024];  __device__ bf16 g_WvTl[(size_t)1024*1024];
__device__ bf16 g_WoTh[(size_t)1024*1088];  __device__ bf16 g_WoTl[(size_t)1024*1088];
__device__ bf16 g_WfcTh[(size_t)4096*1024]; __device__ bf16 g_WfcTl[(size_t)4096*1024];
__device__ bf16 g_WpjTh[(size_t)1024*4096]; __device__ bf16 g_WpjTl[(size_t)1024*4096];

// ======================= small PTX helpers ===================================
__device__ __forceinline__ uint32_t smem_to_u32(const void* smem_ptr) {
    uint32_t addr;
    asm("{ .reg .u64 tmp; cvta.to.shared.u64 tmp, %1; cvt.u32.u64 %0, tmp; }"
        : "=r"(addr) : "l"(smem_ptr));
    return addr;
}
__device__ __forceinline__ void cp16(uint32_t saddr, const void* gptr) {
    asm volatile("cp.async.cg.shared.global [%0], [%1], 16;" :: "r"(saddr), "l"(gptr));
}
__device__ __forceinline__ void cp_commit() {
    asm volatile("cp.async.commit_group;" ::: "memory");
}
__device__ __forceinline__ void ldm_x4(uint32_t* r, uint32_t a) {
    asm volatile("ldmatrix.sync.aligned.m8n8.x4.shared.b16 {%0,%1,%2,%3}, [%4];"
        : "=r"(r[0]), "=r"(r[1]), "=r"(r[2]), "=r"(r[3]) : "r"(a));
}
__device__ __forceinline__ void ldm_x2(uint32_t* r, uint32_t a) {
    asm volatile("ldmatrix.sync.aligned.m8n8.x2.shared.b16 {%0,%1}, [%2];"
        : "=r"(r[0]), "=r"(r[1]) : "r"(a));
}
__device__ __forceinline__ void mma_bf16(float* d, const uint32_t* a, const uint32_t* b) {
    asm volatile(
        "mma.sync.aligned.m16n8k16.row.col.f32.bf16.bf16.f32 "
        "{%0,%1,%2,%3}, {%4,%5,%6,%7}, {%8,%9}, {%0,%1,%2,%3};"
        : "+f"(d[0]), "+f"(d[1]), "+f"(d[2]), "+f"(d[3])
        : "r"(a[0]), "r"(a[1]), "r"(a[2]), "r"(a[3]), "r"(b[0]), "r"(b[1]));
}

// ======================= HMMA 3-pass split GEMM ==============================
// C[M x Nreal] = (Ah+Al)[M,K] @ (Bh+Bl)^T + bias, B stored [Npad][K] K-major.
// Block 128x128x32, 8 warps (2x4), warp tile 64x32, double-buffered cp.async.
#define ROWB  80                  // padded row bytes (40 bf16 per 32-elem row)
#define TILEB (128*ROWB)          // 10240
#define BUFB  (4*TILEB)           // 40960
#define GSMEM (2*BUFB)            // 81920

__global__ __launch_bounds__(256, 1)
void hgemm3(const bf16* __restrict__ Ah, const bf16* __restrict__ Al,
            const bf16* __restrict__ Bh, const bf16* __restrict__ Bl,
            const float* __restrict__ bias, float* __restrict__ C,
            int K, int Nreal, int ldc, int coff) {
    extern __shared__ char smc[];
    uint32_t sb = smem_to_u32(smc);
    int tid = threadIdx.x, lane = tid & 31, wid = tid >> 5;
    int wm = wid >> 2, wn = wid & 3;
    int row0 = blockIdx.y * 128, col0 = blockIdx.x * 128;

    const bf16* gT[4];
    gT[0] = Ah + (size_t)row0 * K;
    gT[1] = Al + (size_t)row0 * K;
    gT[2] = Bh + (size_t)col0 * K;
    gT[3] = Bl + (size_t)col0 * K;

    // per-thread load map: row = tid>>1, two consecutive 16B segs
    int lrow = tid >> 1, lseg = (tid & 1) * 2;
    uint32_t sdst = lrow * ROWB + lseg * 16;
    size_t   gsrc = (size_t)lrow * K + lseg * 8;

    int nslab = K >> 5;

    // preload slab 0
    {
        uint32_t b = sb;
#pragma unroll
        for (int t = 0; t < 4; t++) {
            cp16(b + t * TILEB + sdst,      gT[t] + gsrc);
            cp16(b + t * TILEB + sdst + 16, gT[t] + gsrc + 8);
        }
        cp_commit();
    }

    float acc[4][4][4];
#pragma unroll
    for (int mi = 0; mi < 4; mi++)
#pragma unroll
        for (int ni = 0; ni < 4; ni++)
#pragma unroll
            for (int c = 0; c < 4; c++) acc[mi][ni][c] = 0.f;

    // fragment base addresses (depend only on lane)
    uint32_t a_off = (uint32_t)((wm * 64 + (lane & 15)) * ROWB + (lane >> 4) * 16);
    uint32_t b_off = (uint32_t)((wn * 32 + (lane & 7)) * ROWB + ((lane >> 3) & 1) * 16);

    for (int s = 0; s < nslab; s++) {
        int buf = s & 1;
        if (s + 1 < nslab) {
            uint32_t b = sb + ((s + 1) & 1) * BUFB;
            size_t ofs = gsrc + (size_t)(s + 1) * 32;
#pragma unroll
            for (int t = 0; t < 4; t++) {
                cp16(b + t * TILEB + sdst,      gT[t] + ofs);
                cp16(b + t * TILEB + sdst + 16, gT[t] + ofs + 8);
            }
            cp_commit();
            asm volatile("cp.async.wait_group 1;" ::: "memory");
        } else {
            asm volatile("cp.async.wait_group 0;" ::: "memory");
        }
        __syncthreads();

        uint32_t base = sb + buf * BUFB;
#pragma unroll
        for (int k16 = 0; k16 < 2; k16++) {
            uint32_t ah[4][4], al[4][4], bh[4][2], bl[4][2];
#pragma unroll
            for (int mi = 0; mi < 4; mi++) {
                uint32_t ad = base + a_off + mi * 16 * ROWB + k16 * 32;
                ldm_x4(ah[mi], ad);
                ldm_x4(al[mi], ad + TILEB);
            }
#pragma unroll
            for (int ni = 0; ni < 4; ni++) {
                uint32_t bd = base + 2 * TILEB + b_off + ni * 8 * ROWB + k16 * 32;
                ldm_x2(bh[ni], bd);
                ldm_x2(bl[ni], bd + TILEB);
            }
#pragma unroll
            for (int mi = 0; mi < 4; mi++)
#pragma unroll
                for (int ni = 0; ni < 4; ni++) {
                    mma_bf16(acc[mi][ni], ah[mi], bh[ni]);
                    mma_bf16(acc[mi][ni], ah[mi], bl[ni]);
                    mma_bf16(acc[mi][ni], al[mi], bh[ni]);
                }
        }
        __syncthreads();
    }

    // epilogue: acc -> C (+bias), mask col < Nreal
    int g = lane >> 2, t4 = lane & 3;
#pragma unroll
    for (int mi = 0; mi < 4; mi++) {
        int r0 = row0 + wm * 64 + mi * 16 + g;
#pragma unroll
        for (int ni = 0; ni < 4; ni++) {
            int c = col0 + wn * 32 + ni * 8 + t4 * 2;
            if (c < Nreal) {
                float bse0 = bias[c];
                C[(size_t)r0 * ldc + coff + c]       = acc[mi][ni][0] + bse0;
                C[(size_t)(r0 + 8) * ldc + coff + c] = acc[mi][ni][2] + bse0;
            }
            if (c + 1 < Nreal) {
                float bse1 = bias[c + 1];
                C[(size_t)r0 * ldc + coff + c + 1]       = acc[mi][ni][1] + bse1;
                C[(size_t)(r0 + 8) * ldc + coff + c + 1] = acc[mi][ni][3] + bse1;
            }
        }
    }
}

// ---------------- weight transpose + bf16 hi/lo split ------------------------
__global__ __launch_bounds__(256)
void wsplitT(const float* __restrict__ W, bf16* __restrict__ Th, bf16* __restrict__ Tl,
             int K, int N, int Kpad, int Npad) {
    __shared__ float t[32][33];
    int n0 = blockIdx.x * 32, k0 = blockIdx.y * 32;
    int tx = threadIdx.x & 31, ty = threadIdx.x >> 5;
#pragma unroll
    for (int j = 0; j < 4; j++) {
        int k = k0 + ty + j * 8, n = n0 + tx;
        t[ty + j * 8][tx] = (k < K && n < N) ? W[(size_t)k * N + n] : 0.f;
    }
    __syncthreads();
#pragma unroll
    for (int j = 0; j < 4; j++) {
        int n = n0 + ty + j * 8, k = k0 + tx;
        if (n < Npad && k < Kpad) {
            float v = t[tx][ty + j * 8];
            bf16 h = __float2bfloat16(v);
            bf16 l = __float2bfloat16(v - __bfloat162float(h));
            Th[(size_t)n * Kpad + k] = h;
            Tl[(size_t)n * Kpad + k] = l;
        }
    }
}

// ---------------- block reductions ------------------------------------------
__device__ __forceinline__ float block_sum(float v, float* sm) {
    int lane = threadIdx.x & 31, wid = threadIdx.x >> 5;
#pragma unroll
    for (int o = 16; o; o >>= 1) v += __shfl_down_sync(0xffffffffu, v, o);
    if (lane == 0) sm[wid] = v;
    __syncthreads();
    if (wid == 0) {
        float r = (lane < ((blockDim.x + 31) >> 5)) ? sm[lane] : 0.f;
#pragma unroll
        for (int o = 16; o; o >>= 1) r += __shfl_down_sync(0xffffffffu, r, o);
        if (lane == 0) sm[0] = r;
    }
    __syncthreads();
    float r = sm[0];
    __syncthreads();
    return r;
}
__device__ __forceinline__ float block_max(float v, float* sm) {
    int lane = threadIdx.x & 31, wid = threadIdx.x >> 5;
#pragma unroll
    for (int o = 16; o; o >>= 1) v = fmaxf(v, __shfl_down_sync(0xffffffffu, v, o));
    if (lane == 0) sm[wid] = v;
    __syncthreads();
    if (wid == 0) {
        float r = (lane < ((blockDim.x + 31) >> 5)) ? sm[lane] : -1e30f;
#pragma unroll
        for (int o = 16; o; o >>= 1) r = fmaxf(r, __shfl_down_sync(0xffffffffu, r, o));
        if (lane == 0) sm[0] = r;
    }
    __syncthreads();
    float r = sm[0];
    __syncthreads();
    return r;
}

// ---------------- Lorentz layernorm + lift -> bf16 hi/lo ---------------------
__global__ __launch_bounds__(256)
void lnorm_split(const float* __restrict__ xin, const float* __restrict__ g,
                 const float* __restrict__ be, bf16* __restrict__ oh, bf16* __restrict__ ol) {
    __shared__ float sm[32];
    int t = blockIdx.x, tid = threadIdx.x;
    const float* xr = xin + (size_t)t * DM + 1;
    float v[4]; float s = 0.f;
#pragma unroll
    for (int j = 0; j < 4; j++) {
        int d = tid + j * 256;
        if (d < 1023) { v[j] = xr[d]; s += v[j]; } else v[j] = 0.f;
    }
    s = block_sum(s, sm);
    float mu = s * (1.f / 1023.f);
    float vs = 0.f;
#pragma unroll
    for (int j = 0; j < 4; j++) {
        int d = tid + j * 256;
        if (d < 1023) { float dd = v[j] - mu; vs += dd * dd; }
    }
    vs = block_sum(vs, sm);
    float inv = rsqrtf(vs * (1.f / 1023.f) + 1e-5f);
    float y[4]; float tt = 0.f;
#pragma unroll
    for (int j = 0; j < 4; j++) {
        int d = tid + j * 256;
        if (d < 1023) { y[j] = (v[j] - mu) * inv * g[d] + be[d]; tt += y[j] * y[j]; }
        else y[j] = 0.f;
    }
    tt = block_sum(tt, sm);
#pragma unroll
    for (int j = 0; j < 4; j++) {
        int d = tid + j * 256;
        if (d < 1023) {
            bf16 h = __float2bfloat16(y[j]);
            oh[(size_t)t * DM + 1 + d] = h;
            ol[(size_t)t * DM + 1 + d] = __float2bfloat16(y[j] - __bfloat162float(h));
        }
    }
    if (tid == 0) {
        float tv = sqrtf(tt + 1.f);
        bf16 h = __float2bfloat16(tv);
        oh[(size_t)t * DM] = h;
        ol[(size_t)t * DM] = __float2bfloat16(tv - __bfloat162float(h));
    }
}

// ---------------- per-head time lift for q,k,v ------------------------------
__global__ __launch_bounds__(512)
void qkv_times() {
    int t = blockIdx.x;
    int b = t >> 10, n = t & 1023;
    int h = threadIdx.x >> 5;
    int lane = threadIdx.x & 31;
    const float* rows[3] = { g_q + (size_t)t * DM, g_k + (size_t)t * DM, g_v + (size_t)t * DM };
    float* outs[3] = { g_qt, g_kt, g_vt };
#pragma unroll
    for (int a = 0; a < 3; a++) {
        float v0 = rows[a][h * 64 + lane], v1 = rows[a][h * 64 + 32 + lane];
        float s = v0 * v0 + v1 * v1;
#pragma unroll
        for (int o = 16; o; o >>= 1) s += __shfl_down_sync(0xffffffffu, s, o);
        if (lane == 0) outs[a][((b * NH + h) << 10) + n] = sqrtf(s + 1.0f);
    }
}

// ---------------- attention scores ------------------------------------------
__global__ __launch_bounds__(256)
void attn_scores() {
    int bh = blockIdx.z;
    int b = bh >> 4, h = bh & 15;
    int q0 = blockIdx.y * 64, k0 = blockIdx.x * 64;
    __shared__ float Qs[64][65];
    __shared__ float Ks[64][65];
    int tid = threadIdx.x;
    int d = tid & 63, r4 = tid >> 6;
    size_t baseq = ((size_t)(b * SEQ + q0)) * DM + h * 64;
    size_t basek = ((size_t)(b * SEQ + k0)) * DM + h * 64;
    for (int r = r4; r < 64; r += 4) {
        Qs[d][r] = g_q[baseq + (size_t)r * DM + d];
        Ks[d][r] = g_k[basek + (size_t)r * DM + d];
    }
    __syncthreads();
    int tr = tid >> 4, tc = tid & 15;
    float acc[4][4];
#pragma unroll
    for (int i = 0; i < 4; i++)
#pragma unroll
        for (int j = 0; j < 4; j++) acc[i][j] = 0.f;
#pragma unroll 8
    for (int dd = 0; dd < 64; dd++) {
        float a[4], bb[4];
#pragma unroll
        for (int i = 0; i < 4; i++) a[i]  = Qs[dd][tr * 4 + i];
#pragma unroll
        for (int j = 0; j < 4; j++) bb[j] = Ks[dd][tc * 4 + j];
#pragma unroll
        for (int i = 0; i < 4; i++)
#pragma unroll
            for (int j = 0; j < 4; j++) acc[i][j] += a[i] * bb[j];
    }
    float qtv[4], ktv[4];
#pragma unroll
    for (int i = 0; i < 4; i++) qtv[i] = g_qt[(bh << 10) + q0 + tr * 4 + i];
#pragma unroll
    for (int j = 0; j < 4; j++) ktv[j] = g_kt[(bh << 10) + k0 + tc * 4 + j];
#pragma unroll
    for (int i = 0; i < 4; i++) {
        size_t rowo = ((size_t)(bh << 10) + q0 + tr * 4 + i) * SEQ + k0 + tc * 4;
#pragma unroll
        for (int j = 0; j < 4; j++)
            g_S[rowo + j] = 0.25f + 0.25f * (acc[i][j] - qtv[i] * ktv[j]);
    }
}

// ---------------- row softmax ------------------------------------------------
__global__ __launch_bounds__(256)
void softmax_rows() {
    __shared__ float sm[32];
    size_t row = blockIdx.x;
    float* p = g_S + row * SEQ;
    int tid = threadIdx.x;
    float v[4], mx = -1e30f;
#pragma unroll
    for (int j = 0; j < 4; j++) { v[j] = p[tid + j * 256]; mx = fmaxf(mx, v[j]); }
    mx = block_max(mx, sm);
    float s = 0.f;
#pragma unroll
    for (int j = 0; j < 4; j++) { v[j] = __expf(v[j] - mx); s += v[j]; }
    s = block_sum(s, sm);
    float inv = 1.f / s;
#pragma unroll
    for (int j = 0; j < 4; j++) p[tid + j * 256] = v[j] * inv;
}

// ---------------- PV + Minkowski normalize + scatter to cat (bf16 hi/lo) ----
__global__ __launch_bounds__(256)
void attn_pv() {
    int bh = blockIdx.y;
    int b = bh >> 4, h = bh & 15;
    int q0 = blockIdx.x * 64;
    __shared__ float At[64][65];
    __shared__ float Vt[64][72];
    int tid = threadIdx.x;
    int rg = tid >> 3;
    int p  = tid & 7;
    int c0 = p * 9;
    int nc = (65 - c0 < 9) ? (65 - c0) : 9;
    float acc0[9], acc1[9];
#pragma unroll
    for (int c = 0; c < 9; c++) { acc0[c] = 0.f; acc1[c] = 0.f; }

    int kk = tid & 63, qr = tid >> 6;
    if (tid < 64) {
#pragma unroll
        for (int c = 65; c < 72; c++) Vt[tid][c] = 0.f;
    }
    for (int k0 = 0; k0 < SEQ; k0 += 64) {
        for (int r = qr; r < 64; r += 4) {
            At[r][kk]     = g_S[((size_t)(bh << 10) + q0 + r) * SEQ + k0 + kk];
            Vt[r][1 + kk] = g_v[((size_t)(b * SEQ + k0 + r)) * DM + h * 64 + kk];
        }
        if (tid < 64) Vt[tid][0] = g_vt[(bh << 10) + k0 + tid];
        __syncthreads();
#pragma unroll 4
        for (int k = 0; k < 64; k++) {
            float a0 = At[2 * rg][k], a1 = At[2 * rg + 1][k];
#pragma unroll
            for (int c = 0; c < 9; c++) {
                float vv = Vt[k][c0 + c];
                acc0[c] += a0 * vv;
                acc1[c] += a1 * vv;
            }
        }
        __syncthreads();
    }
    float lin0 = 0.f, lin1 = 0.f;
#pragma unroll
    for (int c = 0; c < 9; c++) {
        if (c < nc) {
            float s0 = acc0[c] * acc0[c], s1 = acc1[c] * acc1[c];
            if (c0 + c == 0) { lin0 -= s0; lin1 -= s1; }
            else             { lin0 += s0; lin1 += s1; }
        }
    }
#pragma unroll
    for (int o = 4; o; o >>= 1) {
        lin0 += __shfl_down_sync(0xffffffffu, lin0, o, 8);
        lin1 += __shfl_down_sync(0xffffffffu, lin1, o, 8);
    }
    lin0 = __shfl_sync(0xffffffffu, lin0, 0, 8);
    lin1 = __shfl_sync(0xffffffffu, lin1, 0, 8);
    float inv0 = rsqrtf(fmaxf(-lin0, 1e-8f));
    float inv1 = rsqrtf(fmaxf(-lin1, 1e-8f));
    size_t o0 = ((size_t)(b * SEQ + q0 + 2 * rg))     * 1088 + h * 65 + c0;
    size_t o1 = ((size_t)(b * SEQ + q0 + 2 * rg + 1)) * 1088 + h * 65 + c0;
#pragma unroll
    for (int c = 0; c < 9; c++) {
        if (c < nc) {
            float v0 = acc0[c] * inv0, v1 = acc1[c] * inv1;
            bf16 h0 = __float2bfloat16(v0), h1v = __float2bfloat16(v1);
            g_cath[o0 + c] = h0;
            g_catl[o0 + c] = __float2bfloat16(v0 - __bfloat162float(h0));
            g_cath[o1 + c] = h1v;
            g_catl[o1 + c] = __float2bfloat16(v1 - __bfloat162float(h1v));
        }
    }
}

// ---------------- Lorentz resnet ---------------------------------------------
__global__ __launch_bounds__(256)
void lresnet_kernel(const float* __restrict__ xin, const float* __restrict__ ysp,
                    const float* __restrict__ wp, float* __restrict__ out) {
    __shared__ float sm[32];
    int t = blockIdx.x, tid = threadIdx.x;
    const float* xr = xin + (size_t)t * DM;
    const float* yr = ysp + (size_t)t * 1023;
    float yv[4]; float ss = 0.f;
#pragma unroll
    for (int j = 0; j < 4; j++) {
        int d = tid + j * 256;
        if (d >= 1) { yv[j] = yr[d - 1]; ss += yv[j] * yv[j]; } else yv[j] = 0.f;
    }
    ss = block_sum(ss, sm);
    float w0 = *wp;
    float ytime = sqrtf(ss + 1.0f);
    float z[4]; float lin = 0.f;
#pragma unroll
    for (int j = 0; j < 4; j++) {
        int d = tid + j * 256;
        float y = (d == 0) ? ytime : yv[j];
        z[j] = xr[d] + w0 * y;
        lin += (d == 0) ? -z[j] * z[j] : z[j] * z[j];
    }
    lin = block_sum(lin, sm);
    float inv = rsqrtf(fmaxf(-lin, 1e-8f));
#pragma unroll
    for (int j = 0; j < 4; j++)
        out[(size_t)t * DM + tid + j * 256] = z[j] * inv;
}

// ---------------- exact GELU + time lift -> bf16 hi/lo ------------------------
__global__ __launch_bounds__(256)
void gelu_split() {
    __shared__ float sm[32];
    int t = blockIdx.x, tid = threadIdx.x;
    const float* r = g_hf + (size_t)t * DFF;
    bf16* oh = g_hfh + (size_t)t * DFF;
    bf16* ol = g_hfl + (size_t)t * DFF;
    float vals[16]; float s = 0.f;
#pragma unroll
    for (int j = 0; j < 16; j++) {
        int d = 1 + tid + j * 256;
        if (d < DFF) {
            float x = r[d];
            float gg = x * normcdff(x);
            vals[j] = gg;
            s += gg * gg;
        } else vals[j] = 0.f;
    }
    s = block_sum(s, sm);
#pragma unroll
    for (int j = 0; j < 16; j++) {
        int d = 1 + tid + j * 256;
        if (d < DFF) {
            bf16 h = __float2bfloat16(vals[j]);
            oh[d] = h;
            ol[d] = __float2bfloat16(vals[j] - __bfloat162float(h));
        }
    }
    if (tid == 0) {
        float tv = sqrtf(s + 1.f);
        bf16 h = __float2bfloat16(tv);
        oh[0] = h;
        ol[0] = __float2bfloat16(tv - __bfloat162float(h));
    }
}

// ---------------- launch ------------------------------------------------------
extern "C" void kernel_launch(void* const* d_in, const int* in_sizes, int n_in,
                              void* d_out, int out_size) {
    const float* x   = (const float*)d_in[0];
    const float* g1  = (const float*)d_in[1];
    const float* b1  = (const float*)d_in[2];
    const float* Wq  = (const float*)d_in[3];
    const float* bq  = (const float*)d_in[4];
    const float* Wk  = (const float*)d_in[5];
    const float* bk  = (const float*)d_in[6];
    const float* Wv  = (const float*)d_in[7];
    const float* bv  = (const float*)d_in[8];
    const float* Wo  = (const float*)d_in[9];
    const float* bo  = (const float*)d_in[10];
    const float* g2  = (const float*)d_in[11];
    const float* b2  = (const float*)d_in[12];
    const float* Wfc = (const float*)d_in[13];
    const float* bfc = (const float*)d_in[14];
    const float* Wpj = (const float*)d_in[15];
    const float* bpj = (const float*)d_in[16];
    const float* w1  = (const float*)d_in[17];
    const float* w2  = (const float*)d_in[18];
    float* out = (float*)d_out;

    cudaFuncSetAttribute(hgemm3, cudaFuncAttributeMaxDynamicSharedMemorySize, GSMEM);

    float *p_q, *p_k, *p_v, *p_ax, *p_x2, *p_hf, *p_pj;
    bf16 *p_lxh, *p_lxl, *p_cath, *p_catl, *p_h1h, *p_h1l, *p_hfh, *p_hfl;
    bf16 *WqTh, *WqTl, *WkTh, *WkTl, *WvTh, *WvTl, *WoTh, *WoTl, *WfcTh, *WfcTl, *WpjTh, *WpjTl;
    cudaGetSymbolAddress((void**)&p_q,   g_q);
    cudaGetSymbolAddress((void**)&p_k,   g_k);
    cudaGetSymbolAddress((void**)&p_v,   g_v);
    cudaGetSymbolAddress((void**)&p_ax,  g_ax);
    cudaGetSymbolAddress((void**)&p_x2,  g_x2);
    cudaGetSymbolAddress((void**)&p_hf,  g_hf);
    cudaGetSymbolAddress((void**)&p_pj,  g_pj);
    cudaGetSymbolAddress((void**)&p_lxh, g_lxh);
    cudaGetSymbolAddress((void**)&p_lxl, g_lxl);
    cudaGetSymbolAddress((void**)&p_cath, g_cath);
    cudaGetSymbolAddress((void**)&p_catl, g_catl);
    cudaGetSymbolAddress((void**)&p_h1h, g_h1h);
    cudaGetSymbolAddress((void**)&p_h1l, g_h1l);
    cudaGetSymbolAddress((void**)&p_hfh, g_hfh);
    cudaGetSymbolAddress((void**)&p_hfl, g_hfl);
    cudaGetSymbolAddress((void**)&WqTh, g_WqTh);  cudaGetSymbolAddress((void**)&WqTl, g_WqTl);
    cudaGetSymbolAddress((void**)&WkTh, g_WkTh);  cudaGetSymbolAddress((void**)&WkTl, g_WkTl);
    cudaGetSymbolAddress((void**)&WvTh, g_WvTh);  cudaGetSymbolAddress((void**)&WvTl, g_WvTl);
    cudaGetSymbolAddress((void**)&WoTh, g_WoTh);  cudaGetSymbolAddress((void**)&WoTl, g_WoTl);
    cudaGetSymbolAddress((void**)&WfcTh, g_WfcTh); cudaGetSymbolAddress((void**)&WfcTl, g_WfcTl);
    cudaGetSymbolAddress((void**)&WpjTh, g_WpjTh); cudaGetSymbolAddress((void**)&WpjTl, g_WpjTl);

    // weight transpose + split
    wsplitT<<<dim3(32, 32), 256>>>(Wq,  WqTh,  WqTl,  1024, 1024, 1024, 1024);
    wsplitT<<<dim3(32, 32), 256>>>(Wk,  WkTh,  WkTl,  1024, 1024, 1024, 1024);
    wsplitT<<<dim3(32, 32), 256>>>(Wv,  WvTh,  WvTl,  1024, 1024, 1024, 1024);
    wsplitT<<<dim3(32, 33), 256>>>(Wo,  WoTh,  WoTl,  1040, 1023, 1088, 1024);
    wsplitT<<<dim3(128, 32), 256>>>(Wfc, WfcTh, WfcTl, 1024, 4095, 1024, 4096);
    wsplitT<<<dim3(32, 128), 256>>>(Wpj, WpjTh, WpjTl, 4096, 1023, 4096, 1024);

    // 1. lx = lorentz_layernorm(x) -> bf16 split
    lnorm_split<<<TOK, 256>>>(x, g1, b1, p_lxh, p_lxl);
    // 2. QKV projections (HMMA 3-pass)
    hgemm3<<<dim3(8, 32), 256, GSMEM>>>(p_lxh, p_lxl, WqTh, WqTl, bq, p_q, 1024, 1024, 1024, 0);
    hgemm3<<<dim3(8, 32), 256, GSMEM>>>(p_lxh, p_lxl, WkTh, WkTl, bk, p_k, 1024, 1024, 1024, 0);
    hgemm3<<<dim3(8, 32), 256, GSMEM>>>(p_lxh, p_lxl, WvTh, WvTl, bv, p_v, 1024, 1024, 1024, 0);
    // 3. per-head time lifts
    qkv_times<<<TOK, 512>>>();
    // 4. attention
    attn_scores<<<dim3(16, 16, BH), 256>>>();
    softmax_rows<<<BH * SEQ, 256>>>();
    attn_pv<<<dim3(16, BH), 256>>>();
    // 5. output projection + first lorentz resnet
    hgemm3<<<dim3(8, 32), 256, GSMEM>>>(p_cath, p_catl, WoTh, WoTl, bo, p_ax, 1088, 1023, 1023, 0);
    lresnet_kernel<<<TOK, 256>>>(x, p_ax, w1, p_x2);
    // 6. MLP branch
    lnorm_split<<<TOK, 256>>>(p_x2, g2, b2, p_h1h, p_h1l);
    hgemm3<<<dim3(32, 32), 256, GSMEM>>>(p_h1h, p_h1l, WfcTh, WfcTl, bfc, p_hf, 1024, 4095, DFF, 1);
    gelu_split<<<TOK, 256>>>();
    hgemm3<<<dim3(8, 32), 256, GSMEM>>>(p_hfh, p_hfl, WpjTh, WpjTl, bpj, p_pj, 4096, 1023, 1023, 0);
    // 7. final lorentz resnet -> output
    lresnet_kernel<<<TOK, 256>>>(p_x2, p_pj, w2, out);
}

// round 6
// speedup vs baseline: 2.4846x; 1.3807x over previous
#include <cuda_runtime.h>
#include <cuda_bf16.h>
#include <math.h>
#include <stdint.h>

#define BATCH 4
#define SEQ   1024
#define DM    1024
#define NH    16
#define HD    64
#define TOK   (BATCH*SEQ)   // 4096
#define BH    (BATCH*NH)    // 64
#define DFF   4096

typedef __nv_bfloat16 bf16;

// ---------------- scratch (device globals; no allocation allowed) -----------
__device__ bf16  g_lxh[(size_t)TOK*DM];
__device__ bf16  g_lxl[(size_t)TOK*DM];
__device__ float g_q  [(size_t)TOK*DM];
__device__ float g_k  [(size_t)TOK*DM];
__device__ float g_v  [(size_t)TOK*DM];
// padded per-head operands for flash attention (88-dim rows, zero pad)
__device__ bf16  g_qph[(size_t)BH*SEQ*88];
__device__ bf16  g_qpl[(size_t)BH*SEQ*88];
__device__ bf16  g_kph[(size_t)BH*SEQ*88];
__device__ bf16  g_kpl[(size_t)BH*SEQ*88];
__device__ bf16  g_vTh[(size_t)BH*72*SEQ];   // [bh][c][n], c=0 time, 1..64 space, 65..71 zero
__device__ bf16  g_vTl[(size_t)BH*72*SEQ];
__device__ bf16  g_cath[(size_t)TOK*1088];   // padded K for Wo gemm (zeros in pad)
__device__ bf16  g_catl[(size_t)TOK*1088];
__device__ float g_ax [(size_t)TOK*1023];
__device__ float g_x2 [(size_t)TOK*DM];
__device__ bf16  g_h1h[(size_t)TOK*DM];
__device__ bf16  g_h1l[(size_t)TOK*DM];
__device__ float g_hf [(size_t)TOK*DFF];
__device__ bf16  g_hfh[(size_t)TOK*DFF];
__device__ bf16  g_hfl[(size_t)TOK*DFF];
__device__ float g_pj [(size_t)TOK*1023];
// transposed/split weights: [Npad][Kpad] K-major bf16 (pads stay zero-init)
__device__ bf16 g_WqTh[(size_t)1024*1024];  __device__ bf16 g_WqTl[(size_t)1024*1024];
__device__ bf16 g_WkTh[(size_t)1024*1024];  __device__ bf16 g_WkTl[(size_t)1024*1024];
__device__ bf16 g_WvTh[(size_t)1024*1024];  __device__ bf16 g_WvTl[(size_t)1024*1024];
__device__ bf16 g_WoTh[(size_t)1024*1088];  __device__ bf16 g_WoTl[(size_t)1024*1088];
__device__ bf16 g_WfcTh[(size_t)4096*1024]; __device__ bf16 g_WfcTl[(size_t)4096*1024];
__device__ bf16 g_WpjTh[(size_t)1024*4096]; __device__ bf16 g_WpjTl[(size_t)1024*4096];

// ======================= small PTX helpers ===================================
__device__ __forceinline__ uint32_t smem_to_u32(const void* smem_ptr) {
    uint32_t addr;
    asm("{ .reg .u64 tmp; cvta.to.shared.u64 tmp, %1; cvt.u32.u64 %0, tmp; }"
        : "=r"(addr) : "l"(smem_ptr));
    return addr;
}
__device__ __forceinline__ void cp16(uint32_t saddr, const void* gptr) {
    asm volatile("cp.async.cg.shared.global [%0], [%1], 16;" :: "r"(saddr), "l"(gptr));
}
__device__ __forceinline__ void cp_commit() {
    asm volatile("cp.async.commit_group;" ::: "memory");
}
__device__ __forceinline__ void ldm_x4(uint32_t* r, uint32_t a) {
    asm volatile("ldmatrix.sync.aligned.m8n8.x4.shared.b16 {%0,%1,%2,%3}, [%4];"
        : "=r"(r[0]), "=r"(r[1]), "=r"(r[2]), "=r"(r[3]) : "r"(a));
}
__device__ __forceinline__ void ldm_x2(uint32_t* r, uint32_t a) {
    asm volatile("ldmatrix.sync.aligned.m8n8.x2.shared.b16 {%0,%1}, [%2];"
        : "=r"(r[0]), "=r"(r[1]) : "r"(a));
}
__device__ __forceinline__ void mma_bf16(float* d, const uint32_t* a, const uint32_t* b) {
    asm volatile(
        "mma.sync.aligned.m16n8k16.row.col.f32.bf16.bf16.f32 "
        "{%0,%1,%2,%3}, {%4,%5,%6,%7}, {%8,%9}, {%0,%1,%2,%3};"
        : "+f"(d[0]), "+f"(d[1]), "+f"(d[2]), "+f"(d[3])
        : "r"(a[0]), "r"(a[1]), "r"(a[2]), "r"(a[3]), "r"(b[0]), "r"(b[1]));
}
__device__ __forceinline__ uint32_t pack_bf2(float a, float b) {
    __nv_bfloat162 t = __floats2bfloat162_rn(a, b);
    return *reinterpret_cast<uint32_t*>(&t);
}

// ======================= HMMA 3-pass split GEMM ==============================
#define ROWB  80
#define TILEB (128*ROWB)
#define BUFB  (4*TILEB)
#define GSMEM (2*BUFB)

__global__ __launch_bounds__(256, 1)
void hgemm3(const bf16* __restrict__ Ah, const bf16* __restrict__ Al,
            const bf16* __restrict__ Bh, const bf16* __restrict__ Bl,
            const float* __restrict__ bias, float* __restrict__ C,
            int K, int Nreal, int ldc, int coff) {
    extern __shared__ char smc[];
    uint32_t sb = smem_to_u32(smc);
    int tid = threadIdx.x, lane = tid & 31, wid = tid >> 5;
    int wm = wid >> 2, wn = wid & 3;
    int row0 = blockIdx.y * 128, col0 = blockIdx.x * 128;

    const bf16* gT[4];
    gT[0] = Ah + (size_t)row0 * K;
    gT[1] = Al + (size_t)row0 * K;
    gT[2] = Bh + (size_t)col0 * K;
    gT[3] = Bl + (size_t)col0 * K;

    int lrow = tid >> 1, lseg = (tid & 1) * 2;
    uint32_t sdst = lrow * ROWB + lseg * 16;
    size_t   gsrc = (size_t)lrow * K + lseg * 8;

    int nslab = K >> 5;
    {
        uint32_t b = sb;
#pragma unroll
        for (int t = 0; t < 4; t++) {
            cp16(b + t * TILEB + sdst,      gT[t] + gsrc);
            cp16(b + t * TILEB + sdst + 16, gT[t] + gsrc + 8);
        }
        cp_commit();
    }

    float acc[4][4][4];
#pragma unroll
    for (int mi = 0; mi < 4; mi++)
#pragma unroll
        for (int ni = 0; ni < 4; ni++)
#pragma unroll
            for (int c = 0; c < 4; c++) acc[mi][ni][c] = 0.f;

    uint32_t a_off = (uint32_t)((wm * 64 + (lane & 15)) * ROWB + (lane >> 4) * 16);
    uint32_t b_off = (uint32_t)((wn * 32 + (lane & 7)) * ROWB + ((lane >> 3) & 1) * 16);

    for (int s = 0; s < nslab; s++) {
        int buf = s & 1;
        if (s + 1 < nslab) {
            uint32_t b = sb + ((s + 1) & 1) * BUFB;
            size_t ofs = gsrc + (size_t)(s + 1) * 32;
#pragma unroll
            for (int t = 0; t < 4; t++) {
                cp16(b + t * TILEB + sdst,      gT[t] + ofs);
                cp16(b + t * TILEB + sdst + 16, gT[t] + ofs + 8);
            }
            cp_commit();
            asm volatile("cp.async.wait_group 1;" ::: "memory");
        } else {
            asm volatile("cp.async.wait_group 0;" ::: "memory");
        }
        __syncthreads();

        uint32_t base = sb + buf * BUFB;
#pragma unroll
        for (int k16 = 0; k16 < 2; k16++) {
            uint32_t ah[4][4], al[4][4], bh[4][2], bl[4][2];
#pragma unroll
            for (int mi = 0; mi < 4; mi++) {
                uint32_t ad = base + a_off + mi * 16 * ROWB + k16 * 32;
                ldm_x4(ah[mi], ad);
                ldm_x4(al[mi], ad + TILEB);
            }
#pragma unroll
            for (int ni = 0; ni < 4; ni++) {
                uint32_t bd = base + 2 * TILEB + b_off + ni * 8 * ROWB + k16 * 32;
                ldm_x2(bh[ni], bd);
                ldm_x2(bl[ni], bd + TILEB);
            }
#pragma unroll
            for (int mi = 0; mi < 4; mi++)
#pragma unroll
                for (int ni = 0; ni < 4; ni++) {
                    mma_bf16(acc[mi][ni], ah[mi], bh[ni]);
                    mma_bf16(acc[mi][ni], ah[mi], bl[ni]);
                    mma_bf16(acc[mi][ni], al[mi], bh[ni]);
                }
        }
        __syncthreads();
    }

    int g = lane >> 2, t4 = lane & 3;
#pragma unroll
    for (int mi = 0; mi < 4; mi++) {
        int r0 = row0 + wm * 64 + mi * 16 + g;
#pragma unroll
        for (int ni = 0; ni < 4; ni++) {
            int c = col0 + wn * 32 + ni * 8 + t4 * 2;
            if (c < Nreal) {
                float bse0 = bias[c];
                C[(size_t)r0 * ldc + coff + c]       = acc[mi][ni][0] + bse0;
                C[(size_t)(r0 + 8) * ldc + coff + c] = acc[mi][ni][2] + bse0;
            }
            if (c + 1 < Nreal) {
                float bse1 = bias[c + 1];
                C[(size_t)r0 * ldc + coff + c + 1]       = acc[mi][ni][1] + bse1;
                C[(size_t)(r0 + 8) * ldc + coff + c + 1] = acc[mi][ni][3] + bse1;
            }
        }
    }
}

// ---------------- weight transpose + bf16 hi/lo split ------------------------
__global__ __launch_bounds__(256)
void wsplitT(const float* __restrict__ W, bf16* __restrict__ Th, bf16* __restrict__ Tl,
             int K, int N, int Kpad, int Npad) {
    __shared__ float t[32][33];
    int n0 = blockIdx.x * 32, k0 = blockIdx.y * 32;
    int tx = threadIdx.x & 31, ty = threadIdx.x >> 5;
#pragma unroll
    for (int j = 0; j < 4; j++) {
        int k = k0 + ty + j * 8, n = n0 + tx;
        t[ty + j * 8][tx] = (k < K && n < N) ? W[(size_t)k * N + n] : 0.f;
    }
    __syncthreads();
#pragma unroll
    for (int j = 0; j < 4; j++) {
        int n = n0 + ty + j * 8, k = k0 + tx;
        if (n < Npad && k < Kpad) {
            float v = t[tx][ty + j * 8];
            bf16 h = __float2bfloat16(v);
            bf16 l = __float2bfloat16(v - __bfloat162float(h));
            Th[(size_t)n * Kpad + k] = h;
            Tl[(size_t)n * Kpad + k] = l;
        }
    }
}

// ---------------- block reductions ------------------------------------------
__device__ __forceinline__ float block_sum(float v, float* sm) {
    int lane = threadIdx.x & 31, wid = threadIdx.x >> 5;
#pragma unroll
    for (int o = 16; o; o >>= 1) v += __shfl_down_sync(0xffffffffu, v, o);
    if (lane == 0) sm[wid] = v;
    __syncthreads();
    if (wid == 0) {
        float r = (lane < ((blockDim.x + 31) >> 5)) ? sm[lane] : 0.f;
#pragma unroll
        for (int o = 16; o; o >>= 1) r += __shfl_down_sync(0xffffffffu, r, o);
        if (lane == 0) sm[0] = r;
    }
    __syncthreads();
    float r = sm[0];
    __syncthreads();
    return r;
}

// ---------------- Lorentz layernorm + lift -> bf16 hi/lo ---------------------
__global__ __launch_bounds__(256)
void lnorm_split(const float* __restrict__ xin, const float* __restrict__ g,
                 const float* __restrict__ be, bf16* __restrict__ oh, bf16* __restrict__ ol) {
    __shared__ float sm[32];
    int t = blockIdx.x, tid = threadIdx.x;
    const float* xr = xin + (size_t)t * DM + 1;
    float v[4]; float s = 0.f;
#pragma unroll
    for (int j = 0; j < 4; j++) {
        int d = tid + j * 256;
        if (d < 1023) { v[j] = xr[d]; s += v[j]; } else v[j] = 0.f;
    }
    s = block_sum(s, sm);
    float mu = s * (1.f / 1023.f);
    float vs = 0.f;
#pragma unroll
    for (int j = 0; j < 4; j++) {
        int d = tid + j * 256;
        if (d < 1023) { float dd = v[j] - mu; vs += dd * dd; }
    }
    vs = block_sum(vs, sm);
    float inv = rsqrtf(vs * (1.f / 1023.f) + 1e-5f);
    float y[4]; float tt = 0.f;
#pragma unroll
    for (int j = 0; j < 4; j++) {
        int d = tid + j * 256;
        if (d < 1023) { y[j] = (v[j] - mu) * inv * g[d] + be[d]; tt += y[j] * y[j]; }
        else y[j] = 0.f;
    }
    tt = block_sum(tt, sm);
#pragma unroll
    for (int j = 0; j < 4; j++) {
        int d = tid + j * 256;
        if (d < 1023) {
            bf16 h = __float2bfloat16(y[j]);
            oh[(size_t)t * DM + 1 + d] = h;
            ol[(size_t)t * DM + 1 + d] = __float2bfloat16(y[j] - __bfloat162float(h));
        }
    }
    if (tid == 0) {
        float tv = sqrtf(tt + 1.f);
        bf16 h = __float2bfloat16(tv);
        oh[(size_t)t * DM] = h;
        ol[(size_t)t * DM] = __float2bfloat16(tv - __bfloat162float(h));
    }
}

// ---------------- qkv prep: build padded q'/k' rows + transposed V' ----------
// q' = [space(64), qt, 0*23], k' = [space, -kt, 0*23]  (88 elems, bf16 hi/lo)
// V'T[bh][c][n]: c=0 time, 1..64 space, 65..71 zero.
__global__ __launch_bounds__(256)
void qkv_prep() {
    __shared__ float sv[64][65];
    __shared__ float svt[64];
    int bh = blockIdx.y;
    int n0 = blockIdx.x * 64;
    int b = bh >> 4, h = bh & 15;
    int tid = threadIdx.x, lane = tid & 31, wid = tid >> 5;

    // phase A: q' and k' rows (each warp: 8 tokens)
#pragma unroll
    for (int j = 0; j < 8; j++) {
        int n = n0 + (wid << 3) + j;
        size_t gin = ((size_t)(b << 10) + n) * DM + h * 64;
        size_t gout = ((size_t)(bh << 10) + n) * 88;
        // q
        {
            float v0 = g_q[gin + lane], v1 = g_q[gin + 32 + lane];
            float s = v0 * v0 + v1 * v1;
#pragma unroll
            for (int o = 16; o; o >>= 1) s += __shfl_xor_sync(0xffffffffu, s, o);
            float qt = sqrtf(s + 1.0f);
            bf16 h0 = __float2bfloat16(v0);
            g_qph[gout + lane] = h0;
            g_qpl[gout + lane] = __float2bfloat16(v0 - __bfloat162float(h0));
            bf16 h1 = __float2bfloat16(v1);
            g_qph[gout + 32 + lane] = h1;
            g_qpl[gout + 32 + lane] = __float2bfloat16(v1 - __bfloat162float(h1));
            if (lane < 24) {
                float pv = (lane == 0) ? qt : 0.f;
                bf16 ph = __float2bfloat16(pv);
                g_qph[gout + 64 + lane] = ph;
                g_qpl[gout + 64 + lane] = __float2bfloat16(pv - __bfloat162float(ph));
            }
        }
        // k (negated time)
        {
            float v0 = g_k[gin + lane], v1 = g_k[gin + 32 + lane];
            float s = v0 * v0 + v1 * v1;
#pragma unroll
            for (int o = 16; o; o >>= 1) s += __shfl_xor_sync(0xffffffffu, s, o);
            float kt = -sqrtf(s + 1.0f);
            bf16 h0 = __float2bfloat16(v0);
            g_kph[gout + lane] = h0;
            g_kpl[gout + lane] = __float2bfloat16(v0 - __bfloat162float(h0));
            bf16 h1 = __float2bfloat16(v1);
            g_kph[gout + 32 + lane] = h1;
            g_kpl[gout + 32 + lane] = __float2bfloat16(v1 - __bfloat162float(h1));
            if (lane < 24) {
                float pv = (lane == 0) ? kt : 0.f;
                bf16 ph = __float2bfloat16(pv);
                g_kph[gout + 64 + lane] = ph;
                g_kpl[gout + 64 + lane] = __float2bfloat16(pv - __bfloat162float(ph));
            }
        }
        // v: stage to smem + time
        {
            int nl = (wid << 3) + j;
            float v0 = g_v[gin + lane], v1 = g_v[gin + 32 + lane];
            sv[nl][lane] = v0; sv[nl][32 + lane] = v1;
            float s = v0 * v0 + v1 * v1;
#pragma unroll
            for (int o = 16; o; o >>= 1) s += __shfl_xor_sync(0xffffffffu, s, o);
            if (lane == 0) svt[nl] = sqrtf(s + 1.0f);
        }
    }
    __syncthreads();
    // phase B: write V'T rows (coalesced over n)
    for (int it = tid; it < 72 * 64; it += 256) {
        int c = it >> 6, nl = it & 63;
        float val = (c == 0) ? svt[nl] : ((c < 65) ? sv[nl][c - 1] : 0.f);
        bf16 hh = __float2bfloat16(val);
        size_t o = ((size_t)bh * 72 + c) * SEQ + n0 + nl;
        g_vTh[o] = hh;
        g_vTl[o] = __float2bfloat16(val - __bfloat162float(hh));
    }
}

// ---------------- flash attention (bf16 3-pass mma, fused softmax) -----------
// grid (16 qtiles, 64 bh), 128 threads (4 warps x 16 q-rows).
#define QRB 176            // smem row bytes for q'/k' (88 bf16 -> 176B, conflict-free)
#define VRB 144            // smem row bytes for V'T (64 bf16 + pad)
#define FS_QH 0
#define FS_QL 11264
#define FS_KH 22528
#define FS_KL 33792
#define FS_VH 45056
#define FS_VL 55424
#define FSMEM 65792

__global__ __launch_bounds__(128)
void flash_attn() {
    extern __shared__ char smf[];
    uint32_t sb = smem_to_u32(smf);
    int bh = blockIdx.y, q0 = blockIdx.x * 64;
    int b = bh >> 4, h = bh & 15;
    int tid = threadIdx.x, lane = tid & 31, wid = tid >> 5;
    int g = lane >> 2, t4 = lane & 3;

    // load Q tile (hi+lo)
    for (int i = tid; i < 704; i += 128) {
        int row = i / 11, seg = i - row * 11;
        size_t gsrc = ((size_t)(bh << 10) + q0 + row) * 88 + seg * 8;
        uint32_t sd = row * QRB + seg * 16;
        cp16(sb + FS_QH + sd, g_qph + gsrc);
        cp16(sb + FS_QL + sd, g_qpl + gsrc);
    }
    cp_commit();

    float acc_o[9][4];
#pragma unroll
    for (int nj = 0; nj < 9; nj++)
#pragma unroll
        for (int e = 0; e < 4; e++) acc_o[nj][e] = 0.f;
    float m_g = -1e30f, m_g8 = -1e30f;

    uint32_t qa_off = (uint32_t)((wid * 16 + (lane & 15)) * QRB + (lane >> 4) * 16);
    uint32_t kb_off = (uint32_t)((lane & 7) * QRB + ((lane >> 3) & 1) * 16);
    uint32_t vb_off = (uint32_t)((lane & 7) * VRB + ((lane >> 3) & 1) * 16);

    for (int kt = 0; kt < 16; kt++) {
        __syncthreads();   // prev compute done; safe to overwrite K/V
        int k0 = kt * 64;
        for (int i = tid; i < 704; i += 128) {
            int row = i / 11, seg = i - row * 11;
            size_t gsrc = ((size_t)(bh << 10) + k0 + row) * 88 + seg * 8;
            uint32_t sd = row * QRB + seg * 16;
            cp16(sb + FS_KH + sd, g_kph + gsrc);
            cp16(sb + FS_KL + sd, g_kpl + gsrc);
        }
        for (int i = tid; i < 648; i += 128) {
            int c = i / 9, seg = i - c * 9;
            size_t gsrc = ((size_t)bh * 72 + c) * SEQ + k0 + seg * 8;
            uint32_t sd = c * VRB + seg * 16;
            cp16(sb + FS_VH + sd, g_vTh + gsrc);
            cp16(sb + FS_VL + sd, g_vTl + gsrc);
        }
        cp_commit();
        asm volatile("cp.async.wait_group 0;" ::: "memory");
        __syncthreads();

        // S = Q'.K'^T (3-pass split), fp32 acc
        float s[8][4];
#pragma unroll
        for (int nj = 0; nj < 8; nj++)
#pragma unroll
            for (int e = 0; e < 4; e++) s[nj][e] = 0.f;
#pragma unroll
        for (int k16 = 0; k16 < 5; k16++) {
            uint32_t aH[4], aL[4];
            ldm_x4(aH, sb + FS_QH + qa_off + k16 * 32);
            ldm_x4(aL, sb + FS_QL + qa_off + k16 * 32);
#pragma unroll
            for (int nj = 0; nj < 8; nj++) {
                uint32_t bHf[2], bLf[2];
                uint32_t bd = kb_off + nj * (8 * QRB) + k16 * 32;
                ldm_x2(bHf, sb + FS_KH + bd);
                ldm_x2(bLf, sb + FS_KL + bd);
                mma_bf16(s[nj], aH, bHf);
                mma_bf16(s[nj], aH, bLf);
                mma_bf16(s[nj], aL, bHf);
            }
        }
        // scores + online max (softmax denom cancels in Minkowski normalize)
        float mt_g = -1e30f, mt_g8 = -1e30f;
#pragma unroll
        for (int nj = 0; nj < 8; nj++) {
            s[nj][0] = fmaf(0.25f, s[nj][0], 0.25f);
            s[nj][1] = fmaf(0.25f, s[nj][1], 0.25f);
            s[nj][2] = fmaf(0.25f, s[nj][2], 0.25f);
            s[nj][3] = fmaf(0.25f, s[nj][3], 0.25f);
            mt_g  = fmaxf(mt_g,  fmaxf(s[nj][0], s[nj][1]));
            mt_g8 = fmaxf(mt_g8, fmaxf(s[nj][2], s[nj][3]));
        }
        mt_g  = fmaxf(mt_g,  __shfl_xor_sync(0xffffffffu, mt_g, 1));
        mt_g  = fmaxf(mt_g,  __shfl_xor_sync(0xffffffffu, mt_g, 2));
        mt_g8 = fmaxf(mt_g8, __shfl_xor_sync(0xffffffffu, mt_g8, 1));
        mt_g8 = fmaxf(mt_g8, __shfl_xor_sync(0xffffffffu, mt_g8, 2));
        float mn_g = fmaxf(m_g, mt_g), mn_g8 = fmaxf(m_g8, mt_g8);
        float sc_g = __expf(m_g - mn_g), sc_g8 = __expf(m_g8 - mn_g8);
        m_g = mn_g; m_g8 = mn_g8;
#pragma unroll
        for (int nj = 0; nj < 8; nj++) {
            s[nj][0] = __expf(s[nj][0] - mn_g);
            s[nj][1] = __expf(s[nj][1] - mn_g);
            s[nj][2] = __expf(s[nj][2] - mn_g8);
            s[nj][3] = __expf(s[nj][3] - mn_g8);
        }
#pragma unroll
        for (int nj = 0; nj < 9; nj++) {
            acc_o[nj][0] *= sc_g;  acc_o[nj][1] *= sc_g;
            acc_o[nj][2] *= sc_g8; acc_o[nj][3] *= sc_g8;
        }
        // O += P.V' (3-pass with P residual)
#pragma unroll
        for (int k16 = 0; k16 < 4; k16++) {
            int u0 = 2 * k16, u1 = u0 + 1;
            uint32_t pH[4], pL[4];
            pH[0] = pack_bf2(s[u0][0], s[u0][1]);
            pH[1] = pack_bf2(s[u0][2], s[u0][3]);
            pH[2] = pack_bf2(s[u1][0], s[u1][1]);
            pH[3] = pack_bf2(s[u1][2], s[u1][3]);
            {
                __nv_bfloat162 t0 = *reinterpret_cast<__nv_bfloat162*>(&pH[0]);
                __nv_bfloat162 t1 = *reinterpret_cast<__nv_bfloat162*>(&pH[1]);
                __nv_bfloat162 t2 = *reinterpret_cast<__nv_bfloat162*>(&pH[2]);
                __nv_bfloat162 t3 = *reinterpret_cast<__nv_bfloat162*>(&pH[3]);
                pL[0] = pack_bf2(s[u0][0] - __bfloat162float(__low2bfloat16(t0)),
                                 s[u0][1] - __bfloat162float(__high2bfloat16(t0)));
                pL[1] = pack_bf2(s[u0][2] - __bfloat162float(__low2bfloat16(t1)),
                                 s[u0][3] - __bfloat162float(__high2bfloat16(t1)));
                pL[2] = pack_bf2(s[u1][0] - __bfloat162float(__low2bfloat16(t2)),
                                 s[u1][1] - __bfloat162float(__high2bfloat16(t2)));
                pL[3] = pack_bf2(s[u1][2] - __bfloat162float(__low2bfloat16(t3)),
                                 s[u1][3] - __bfloat162float(__high2bfloat16(t3)));
            }
#pragma unroll
            for (int nj = 0; nj < 9; nj++) {
                uint32_t bHf[2], bLf[2];
                uint32_t bd = vb_off + nj * (8 * VRB) + k16 * 32;
                ldm_x2(bHf, sb + FS_VH + bd);
                ldm_x2(bLf, sb + FS_VL + bd);
                mma_bf16(acc_o[nj], pH, bHf);
                mma_bf16(acc_o[nj], pH, bLf);
                mma_bf16(acc_o[nj], pL, bHf);
            }
        }
    }

    // Minkowski normalize (softmax 1/l cancels), write to cat (bf16 hi/lo)
    float d_g = 0.f, d_g8 = 0.f;   // t^2 - sum(space^2)
#pragma unroll
    for (int nj = 0; nj < 9; nj++) {
#pragma unroll
        for (int e = 0; e < 2; e++) {
            int c = nj * 8 + 2 * t4 + e;
            float o0 = acc_o[nj][e], o1 = acc_o[nj][e + 2];
            float sgn = (c == 0) ? 1.f : -1.f;
            d_g  += sgn * o0 * o0;
            d_g8 += sgn * o1 * o1;
        }
    }
    d_g  += __shfl_xor_sync(0xffffffffu, d_g, 1);
    d_g  += __shfl_xor_sync(0xffffffffu, d_g, 2);
    d_g8 += __shfl_xor_sync(0xffffffffu, d_g8, 1);
    d_g8 += __shfl_xor_sync(0xffffffffu, d_g8, 2);
    float inv_g  = rsqrtf(fmaxf(d_g,  1e-8f));
    float inv_g8 = rsqrtf(fmaxf(d_g8, 1e-8f));

    int n_g  = q0 + wid * 16 + g;
    size_t tok_g  = (size_t)(b << 10) + n_g;
    size_t o_g  = tok_g * 1088 + h * 65;
    size_t o_g8 = (tok_g + 8) * 1088 + h * 65;
#pragma unroll
    for (int nj = 0; nj < 9; nj++) {
#pragma unroll
        for (int e = 0; e < 2; e++) {
            int c = nj * 8 + 2 * t4 + e;
            if (c < 65) {
                float v0 = acc_o[nj][e] * inv_g;
                bf16 h0 = __float2bfloat16(v0);
                g_cath[o_g + c] = h0;
                g_catl[o_g + c] = __float2bfloat16(v0 - __bfloat162float(h0));
                float v1 = acc_o[nj][e + 2] * inv_g8;
                bf16 h1v = __float2bfloat16(v1);
                g_cath[o_g8 + c] = h1v;
                g_catl[o_g8 + c] = __float2bfloat16(v1 - __bfloat162float(h1v));
            }
        }
    }
}

// ---------------- Lorentz resnet ---------------------------------------------
__global__ __launch_bounds__(256)
void lresnet_kernel(const float* __restrict__ xin, const float* __restrict__ ysp,
                    const float* __restrict__ wp, float* __restrict__ out) {
    __shared__ float sm[32];
    int t = blockIdx.x, tid = threadIdx.x;
    const float* xr = xin + (size_t)t * DM;
    const float* yr = ysp + (size_t)t * 1023;
    float yv[4]; float ss = 0.f;
#pragma unroll
    for (int j = 0; j < 4; j++) {
        int d = tid + j * 256;
        if (d >= 1) { yv[j] = yr[d - 1]; ss += yv[j] * yv[j]; } else yv[j] = 0.f;
    }
    ss = block_sum(ss, sm);
    float w0 = *wp;
    float ytime = sqrtf(ss + 1.0f);
    float z[4]; float lin = 0.f;
#pragma unroll
    for (int j = 0; j < 4; j++) {
        int d = tid + j * 256;
        float y = (d == 0) ? ytime : yv[j];
        z[j] = xr[d] + w0 * y;
        lin += (d == 0) ? -z[j] * z[j] : z[j] * z[j];
    }
    lin = block_sum(lin, sm);
    float inv = rsqrtf(fmaxf(-lin, 1e-8f));
#pragma unroll
    for (int j = 0; j < 4; j++)
        out[(size_t)t * DM + tid + j * 256] = z[j] * inv;
}

// ---------------- exact GELU + time lift -> bf16 hi/lo ------------------------
__global__ __launch_bounds__(256)
void gelu_split() {
    __shared__ float sm[32];
    int t = blockIdx.x, tid = threadIdx.x;
    const float* r = g_hf + (size_t)t * DFF;
    bf16* oh = g_hfh + (size_t)t * DFF;
    bf16* ol = g_hfl + (size_t)t * DFF;
    float vals[16]; float s = 0.f;
#pragma unroll
    for (int j = 0; j < 16; j++) {
        int d = 1 + tid + j * 256;
        if (d < DFF) {
            float x = r[d];
            float gg = x * normcdff(x);
            vals[j] = gg;
            s += gg * gg;
        } else vals[j] = 0.f;
    }
    s = block_sum(s, sm);
#pragma unroll
    for (int j = 0; j < 16; j++) {
        int d = 1 + tid + j * 256;
        if (d < DFF) {
            bf16 h = __float2bfloat16(vals[j]);
            oh[d] = h;
            ol[d] = __float2bfloat16(vals[j] - __bfloat162float(h));
        }
    }
    if (tid == 0) {
        float tv = sqrtf(s + 1.f);
        bf16 h = __float2bfloat16(tv);
        oh[0] = h;
        ol[0] = __float2bfloat16(tv - __bfloat162float(h));
    }
}

// ---------------- launch ------------------------------------------------------
extern "C" void kernel_launch(void* const* d_in, const int* in_sizes, int n_in,
                              void* d_out, int out_size) {
    const float* x   = (const float*)d_in[0];
    const float* g1  = (const float*)d_in[1];
    const float* b1  = (const float*)d_in[2];
    const float* Wq  = (const float*)d_in[3];
    const float* bq  = (const float*)d_in[4];
    const float* Wk  = (const float*)d_in[5];
    const float* bk  = (const float*)d_in[6];
    const float* Wv  = (const float*)d_in[7];
    const float* bv  = (const float*)d_in[8];
    const float* Wo  = (const float*)d_in[9];
    const float* bo  = (const float*)d_in[10];
    const float* g2  = (const float*)d_in[11];
    const float* b2  = (const float*)d_in[12];
    const float* Wfc = (const float*)d_in[13];
    const float* bfc = (const float*)d_in[14];
    const float* Wpj = (const float*)d_in[15];
    const float* bpj = (const float*)d_in[16];
    const float* w1  = (const float*)d_in[17];
    const float* w2  = (const float*)d_in[18];
    float* out = (float*)d_out;

    cudaFuncSetAttribute(hgemm3, cudaFuncAttributeMaxDynamicSharedMemorySize, GSMEM);
    cudaFuncSetAttribute(flash_attn, cudaFuncAttributeMaxDynamicSharedMemorySize, FSMEM);

    float *p_q, *p_k, *p_v, *p_ax, *p_x2, *p_hf, *p_pj;
    bf16 *p_lxh, *p_lxl, *p_cath, *p_catl, *p_h1h, *p_h1l, *p_hfh, *p_hfl;
    bf16 *WqTh, *WqTl, *WkTh, *WkTl, *WvTh, *WvTl, *WoTh, *WoTl, *WfcTh, *WfcTl, *WpjTh, *WpjTl;
    cudaGetSymbolAddress((void**)&p_q,   g_q);
    cudaGetSymbolAddress((void**)&p_k,   g_k);
    cudaGetSymbolAddress((void**)&p_v,   g_v);
    cudaGetSymbolAddress((void**)&p_ax,  g_ax);
    cudaGetSymbolAddress((void**)&p_x2,  g_x2);
    cudaGetSymbolAddress((void**)&p_hf,  g_hf);
    cudaGetSymbolAddress((void**)&p_pj,  g_pj);
    cudaGetSymbolAddress((void**)&p_lxh, g_lxh);
    cudaGetSymbolAddress((void**)&p_lxl, g_lxl);
    cudaGetSymbolAddress((void**)&p_cath, g_cath);
    cudaGetSymbolAddress((void**)&p_catl, g_catl);
    cudaGetSymbolAddress((void**)&p_h1h, g_h1h);
    cudaGetSymbolAddress((void**)&p_h1l, g_h1l);
    cudaGetSymbolAddress((void**)&p_hfh, g_hfh);
    cudaGetSymbolAddress((void**)&p_hfl, g_hfl);
    cudaGetSymbolAddress((void**)&WqTh, g_WqTh);  cudaGetSymbolAddress((void**)&WqTl, g_WqTl);
    cudaGetSymbolAddress((void**)&WkTh, g_WkTh);  cudaGetSymbolAddress((void**)&WkTl, g_WkTl);
    cudaGetSymbolAddress((void**)&WvTh, g_WvTh);  cudaGetSymbolAddress((void**)&WvTl, g_WvTl);
    cudaGetSymbolAddress((void**)&WoTh, g_WoTh);  cudaGetSymbolAddress((void**)&WoTl, g_WoTl);
    cudaGetSymbolAddress((void**)&WfcTh, g_WfcTh); cudaGetSymbolAddress((void**)&WfcTl, g_WfcTl);
    cudaGetSymbolAddress((void**)&WpjTh, g_WpjTh); cudaGetSymbolAddress((void**)&WpjTl, g_WpjTl);

    // weight transpose + split
    wsplitT<<<dim3(32, 32), 256>>>(Wq,  WqTh,  WqTl,  1024, 1024, 1024, 1024);
    wsplitT<<<dim3(32, 32), 256>>>(Wk,  WkTh,  WkTl,  1024, 1024, 1024, 1024);
    wsplitT<<<dim3(32, 32), 256>>>(Wv,  WvTh,  WvTl,  1024, 1024, 1024, 1024);
    wsplitT<<<dim3(32, 33), 256>>>(Wo,  WoTh,  WoTl,  1040, 1023, 1088, 1024);
    wsplitT<<<dim3(128, 32), 256>>>(Wfc, WfcTh, WfcTl, 1024, 4095, 1024, 4096);
    wsplitT<<<dim3(32, 128), 256>>>(Wpj, WpjTh, WpjTl, 4096, 1023, 4096, 1024);

    // 1. lx = lorentz_layernorm(x) -> bf16 split
    lnorm_split<<<TOK, 256>>>(x, g1, b1, p_lxh, p_lxl);
    // 2. QKV projections (HMMA 3-pass)
    hgemm3<<<dim3(8, 32), 256, GSMEM>>>(p_lxh, p_lxl, WqTh, WqTl, bq, p_q, 1024, 1024, 1024, 0);
    hgemm3<<<dim3(8, 32), 256, GSMEM>>>(p_lxh, p_lxl, WkTh, WkTl, bk, p_k, 1024, 1024, 1024, 0);
    hgemm3<<<dim3(8, 32), 256, GSMEM>>>(p_lxh, p_lxl, WvTh, WvTl, bv, p_v, 1024, 1024, 1024, 0);
    // 3. build padded/split attention operands
    qkv_prep<<<dim3(16, BH), 256>>>();
    // 4. fused flash attention -> cat (bf16 hi/lo)
    flash_attn<<<dim3(16, BH), 128, FSMEM>>>();
    // 5. output projection + first lorentz resnet
    hgemm3<<<dim3(8, 32), 256, GSMEM>>>(p_cath, p_catl, WoTh, WoTl, bo, p_ax, 1088, 1023, 1023, 0);
    lresnet_kernel<<<TOK, 256>>>(x, p_ax, w1, p_x2);
    // 6. MLP branch
    lnorm_split<<<TOK, 256>>>(p_x2, g2, b2, p_h1h, p_h1l);
    hgemm3<<<dim3(32, 32), 256, GSMEM>>>(p_h1h, p_h1l, WfcTh, WfcTl, bfc, p_hf, 1024, 4095, DFF, 1);
    gelu_split<<<TOK, 256>>>();
    hgemm3<<<dim3(8, 32), 256, GSMEM>>>(p_hfh, p_hfl, WpjTh, WpjTl, bpj, p_pj, 4096, 1023, 1023, 0);
    // 7. final lorentz resnet -> output
    lresnet_kernel<<<TOK, 256>>>(p_x2, p_pj, w2, out);
}

// round 10
// speedup vs baseline: 2.7621x; 1.1117x over previous
#include <cuda_runtime.h>
#include <cuda_bf16.h>
#include <math.h>
#include <stdint.h>

#define BATCH 4
#define SEQ   1024
#define DM    1024
#define NH    16
#define HD    64
#define TOK   (BATCH*SEQ)   // 4096
#define BH    (BATCH*NH)    // 64
#define DFF   4096

typedef __nv_bfloat16 bf16;

// ---------------- scratch (device globals; no allocation allowed) -----------
__device__ bf16  g_lxh[(size_t)TOK*DM];
__device__ bf16  g_lxl[(size_t)TOK*DM];
__device__ float g_qkv[(size_t)3*TOK*DM];     // [region(q,k,v)][tok][dim]
// padded per-head operands for flash attention (88-dim rows, zero pad)
__device__ bf16  g_qph[(size_t)BH*SEQ*88];
__device__ bf16  g_qpl[(size_t)BH*SEQ*88];
__device__ bf16  g_kph[(size_t)BH*SEQ*88];
__device__ bf16  g_kpl[(size_t)BH*SEQ*88];
__device__ bf16  g_vTh[(size_t)BH*72*SEQ];   // [bh][c][n], c=0 time, 1..64 space, 65..71 zero
__device__ bf16  g_vTl[(size_t)BH*72*SEQ];
__device__ bf16  g_cath[(size_t)TOK*1088];   // padded K for Wo gemm (zeros in pad)
__device__ bf16  g_catl[(size_t)TOK*1088];
__device__ float g_ax [(size_t)TOK*1023];
__device__ float g_x2 [(size_t)TOK*DM];
__device__ bf16  g_h1h[(size_t)TOK*DM];
__device__ bf16  g_h1l[(size_t)TOK*DM];
__device__ float g_hf [(size_t)TOK*DFF];
__device__ bf16  g_hfh[(size_t)TOK*DFF];
__device__ bf16  g_hfl[(size_t)TOK*DFF];
__device__ float g_pj [(size_t)TOK*1023];
__device__ float g_bqkv[3072];
// transposed/split weights: [Npad][Kpad] K-major bf16 (pads stay zero-init)
__device__ bf16 g_Wqkvh[(size_t)3072*1024]; __device__ bf16 g_Wqkvl[(size_t)3072*1024];
__device__ bf16 g_WoTh[(size_t)1024*1088];  __device__ bf16 g_WoTl[(size_t)1024*1088];
__device__ bf16 g_WfcTh[(size_t)4096*1024]; __device__ bf16 g_WfcTl[(size_t)4096*1024];
__device__ bf16 g_WpjTh[(size_t)1024*4096]; __device__ bf16 g_WpjTl[(size_t)1024*4096];

// ======================= small PTX helpers ===================================
__device__ __forceinline__ uint32_t smem_to_u32(const void* smem_ptr) {
    uint32_t addr;
    asm("{ .reg .u64 tmp; cvta.to.shared.u64 tmp, %1; cvt.u32.u64 %0, tmp; }"
        : "=r"(addr) : "l"(smem_ptr));
    return addr;
}
__device__ __forceinline__ void cp16(uint32_t saddr, const void* gptr) {
    asm volatile("cp.async.cg.shared.global [%0], [%1], 16;" :: "r"(saddr), "l"(gptr));
}
__device__ __forceinline__ void cp_commit() {
    asm volatile("cp.async.commit_group;" ::: "memory");
}
__device__ __forceinline__ void ldm_x4(uint32_t* r, uint32_t a) {
    asm volatile("ldmatrix.sync.aligned.m8n8.x4.shared.b16 {%0,%1,%2,%3}, [%4];"
        : "=r"(r[0]), "=r"(r[1]), "=r"(r[2]), "=r"(r[3]) : "r"(a));
}
__device__ __forceinline__ void ldm_x2(uint32_t* r, uint32_t a) {
    asm volatile("ldmatrix.sync.aligned.m8n8.x2.shared.b16 {%0,%1}, [%2];"
        : "=r"(r[0]), "=r"(r[1]) : "r"(a));
}
__device__ __forceinline__ void mma_bf16(float* d, const uint32_t* a, const uint32_t* b) {
    asm volatile(
        "mma.sync.aligned.m16n8k16.row.col.f32.bf16.bf16.f32 "
        "{%0,%1,%2,%3}, {%4,%5,%6,%7}, {%8,%9}, {%0,%1,%2,%3};"
        : "+f"(d[0]), "+f"(d[1]), "+f"(d[2]), "+f"(d[3])
        : "r"(a[0]), "r"(a[1]), "r"(a[2]), "r"(a[3]), "r"(b[0]), "r"(b[1]));
}
__device__ __forceinline__ uint32_t pack_bf2(float a, float b) {
    __nv_bfloat162 t = __floats2bfloat162_rn(a, b);
    return *reinterpret_cast<uint32_t*>(&t);
}

// ======================= HMMA 3-pass split GEMM ==============================
// cmode 0: C[row*ldc + coff + col]            (col < Nreal)
// cmode 1: C[((col>>10)*TOK + row)*1024 + (col&1023)]   (qkv fused)
#define ROWB  80
#define TILEB (128*ROWB)
#define BUFB  (4*TILEB)
#define GSMEM (2*BUFB)

__global__ __launch_bounds__(256, 2)
void hgemm3(const bf16* __restrict__ Ah, const bf16* __restrict__ Al,
            const bf16* __restrict__ Bh, const bf16* __restrict__ Bl,
            const float* __restrict__ bias, float* __restrict__ C,
            int K, int Nreal, int ldc, int coff, int cmode) {
    extern __shared__ char smc[];
    uint32_t sb = smem_to_u32(smc);
    int tid = threadIdx.x, lane = tid & 31, wid = tid >> 5;
    int wm = wid >> 2, wn = wid & 3;
    int row0 = blockIdx.y * 128, col0 = blockIdx.x * 128;

    const bf16* gT[4];
    gT[0] = Ah + (size_t)row0 * K;
    gT[1] = Al + (size_t)row0 * K;
    gT[2] = Bh + (size_t)col0 * K;
    gT[3] = Bl + (size_t)col0 * K;

    int lrow = tid >> 1, lseg = (tid & 1) * 2;
    uint32_t sdst = lrow * ROWB + lseg * 16;
    size_t   gsrc = (size_t)lrow * K + lseg * 8;

    int nslab = K >> 5;
    {
        uint32_t b = sb;
#pragma unroll
        for (int t = 0; t < 4; t++) {
            cp16(b + t * TILEB + sdst,      gT[t] + gsrc);
            cp16(b + t * TILEB + sdst + 16, gT[t] + gsrc + 8);
        }
        cp_commit();
    }

    float acc[4][4][4];
#pragma unroll
    for (int mi = 0; mi < 4; mi++)
#pragma unroll
        for (int ni = 0; ni < 4; ni++)
#pragma unroll
            for (int c = 0; c < 4; c++) acc[mi][ni][c] = 0.f;

    uint32_t a_off = (uint32_t)((wm * 64 + (lane & 15)) * ROWB + (lane >> 4) * 16);
    uint32_t b_off = (uint32_t)((wn * 32 + (lane & 7)) * ROWB + ((lane >> 3) & 1) * 16);

    for (int s = 0; s < nslab; s++) {
        int buf = s & 1;
        if (s + 1 < nslab) {
            uint32_t b = sb + ((s + 1) & 1) * BUFB;
            size_t ofs = gsrc + (size_t)(s + 1) * 32;
#pragma unroll
            for (int t = 0; t < 4; t++) {
                cp16(b + t * TILEB + sdst,      gT[t] + ofs);
                cp16(b + t * TILEB + sdst + 16, gT[t] + ofs + 8);
            }
            cp_commit();
            asm volatile("cp.async.wait_group 1;" ::: "memory");
        } else {
            asm volatile("cp.async.wait_group 0;" ::: "memory");
        }
        __syncthreads();

        uint32_t base = sb + buf * BUFB;
#pragma unroll
        for (int k16 = 0; k16 < 2; k16++) {
            uint32_t ah[4][4], al[4][4];
#pragma unroll
            for (int mi = 0; mi < 4; mi++) {
                uint32_t ad = base + a_off + mi * 16 * ROWB + k16 * 32;
                ldm_x4(ah[mi], ad);
                ldm_x4(al[mi], ad + TILEB);
            }
#pragma unroll
            for (int ni = 0; ni < 4; ni++) {
                uint32_t bh[2], bl[2];
                uint32_t bd = base + 2 * TILEB + b_off + ni * 8 * ROWB + k16 * 32;
                ldm_x2(bh, bd);
                ldm_x2(bl, bd + TILEB);
#pragma unroll
                for (int mi = 0; mi < 4; mi++) {
                    mma_bf16(acc[mi][ni], ah[mi], bh);
                    mma_bf16(acc[mi][ni], ah[mi], bl);
                    mma_bf16(acc[mi][ni], al[mi], bh);
                }
            }
        }
        __syncthreads();
    }

    int g = lane >> 2, t4 = lane & 3;
#pragma unroll
    for (int mi = 0; mi < 4; mi++) {
        int r0 = row0 + wm * 64 + mi * 16 + g;
#pragma unroll
        for (int ni = 0; ni < 4; ni++) {
            int c = col0 + wn * 32 + ni * 8 + t4 * 2;
#pragma unroll
            for (int e = 0; e < 2; e++) {
                int cc = c + e;
                if (cc < Nreal) {
                    float bs = bias[cc];
                    size_t i0, i1;
                    if (cmode) {
                        size_t rb = ((size_t)(cc >> 10) * TOK) * 1024 + (cc & 1023);
                        i0 = rb + (size_t)r0 * 1024;
                        i1 = rb + (size_t)(r0 + 8) * 1024;
                    } else {
                        i0 = (size_t)r0 * ldc + coff + cc;
                        i1 = (size_t)(r0 + 8) * ldc + coff + cc;
                    }
                    C[i0] = acc[mi][ni][e]     + bs;
                    C[i1] = acc[mi][ni][e + 2] + bs;
                }
            }
        }
    }
}

// ---------------- weight transpose + bf16 hi/lo split ------------------------
__global__ __launch_bounds__(256)
void wsplitT(const float* __restrict__ W, bf16* __restrict__ Th, bf16* __restrict__ Tl,
             int K, int N, int Kpad, int Npad) {
    __shared__ float t[32][33];
    int n0 = blockIdx.x * 32, k0 = blockIdx.y * 32;
    int tx = threadIdx.x & 31, ty = threadIdx.x >> 5;
#pragma unroll
    for (int j = 0; j < 4; j++) {
        int k = k0 + ty + j * 8, n = n0 + tx;
        t[ty + j * 8][tx] = (k < K && n < N) ? W[(size_t)k * N + n] : 0.f;
    }
    __syncthreads();
#pragma unroll
    for (int j = 0; j < 4; j++) {
        int n = n0 + ty + j * 8, k = k0 + tx;
        if (n < Npad && k < Kpad) {
            float v = t[tx][ty + j * 8];
            bf16 h = __float2bfloat16(v);
            bf16 l = __float2bfloat16(v - __bfloat162float(h));
            Th[(size_t)n * Kpad + k] = h;
            Tl[(size_t)n * Kpad + k] = l;
        }
    }
}

// ---------------- concat qkv bias --------------------------------------------
__global__ void biascat(const float* bq, const float* bk, const float* bv) {
    int i = blockIdx.x * 256 + threadIdx.x;
    if (i < 1024)      g_bqkv[i] = bq[i];
    else if (i < 2048) g_bqkv[i] = bk[i - 1024];
    else if (i < 3072) g_bqkv[i] = bv[i - 2048];
}

// ---------------- block reductions ------------------------------------------
__device__ __forceinline__ float block_sum(float v, float* sm) {
    int lane = threadIdx.x & 31, wid = threadIdx.x >> 5;
#pragma unroll
    for (int o = 16; o; o >>= 1) v += __shfl_down_sync(0xffffffffu, v, o);
    if (lane == 0) sm[wid] = v;
    __syncthreads();
    if (wid == 0) {
        float r = (lane < ((blockDim.x + 31) >> 5)) ? sm[lane] : 0.f;
#pragma unroll
        for (int o = 16; o; o >>= 1) r += __shfl_down_sync(0xffffffffu, r, o);
        if (lane == 0) sm[0] = r;
    }
    __syncthreads();
    float r = sm[0];
    __syncthreads();
    return r;
}

// ---------------- Lorentz layernorm + lift -> bf16 hi/lo ---------------------
__global__ __launch_bounds__(256)
void lnorm_split(const float* __restrict__ xin, const float* __restrict__ g,
                 const float* __restrict__ be, bf16* __restrict__ oh, bf16* __restrict__ ol) {
    __shared__ float sm[32];
    int t = blockIdx.x, tid = threadIdx.x;
    const float* xr = xin + (size_t)t * DM + 1;
    float v[4]; float s = 0.f;
#pragma unroll
    for (int j = 0; j < 4; j++) {
        int d = tid + j * 256;
        if (d < 1023) { v[j] = xr[d]; s += v[j]; } else v[j] = 0.f;
    }
    s = block_sum(s, sm);
    float mu = s * (1.f / 1023.f);
    float vs = 0.f;
#pragma unroll
    for (int j = 0; j < 4; j++) {
        int d = tid + j * 256;
        if (d < 1023) { float dd = v[j] - mu; vs += dd * dd; }
    }
    vs = block_sum(vs, sm);
    float inv = rsqrtf(vs * (1.f / 1023.f) + 1e-5f);
    float y[4]; float tt = 0.f;
#pragma unroll
    for (int j = 0; j < 4; j++) {
        int d = tid + j * 256;
        if (d < 1023) { y[j] = (v[j] - mu) * inv * g[d] + be[d]; tt += y[j] * y[j]; }
        else y[j] = 0.f;
    }
    tt = block_sum(tt, sm);
#pragma unroll
    for (int j = 0; j < 4; j++) {
        int d = tid + j * 256;
        if (d < 1023) {
            bf16 h = __float2bfloat16(y[j]);
            oh[(size_t)t * DM + 1 + d] = h;
            ol[(size_t)t * DM + 1 + d] = __float2bfloat16(y[j] - __bfloat162float(h));
        }
    }
    if (tid == 0) {
        float tv = sqrtf(tt + 1.f);
        bf16 h = __float2bfloat16(tv);
        oh[(size_t)t * DM] = h;
        ol[(size_t)t * DM] = __float2bfloat16(tv - __bfloat162float(h));
    }
}

// ---------------- qkv prep: build padded q'/k' rows + transposed V' ----------
__global__ __launch_bounds__(256)
void qkv_prep() {
    __shared__ float sv[64][65];
    __shared__ float svt[64];
    int bh = blockIdx.y;
    int n0 = blockIdx.x * 64;
    int b = bh >> 4, h = bh & 15;
    int tid = threadIdx.x, lane = tid & 31, wid = tid >> 5;

    const float* gq = g_qkv;
    const float* gk = g_qkv + (size_t)TOK * DM;
    const float* gv = g_qkv + (size_t)2 * TOK * DM;

#pragma unroll
    for (int j = 0; j < 8; j++) {
        int n = n0 + (wid << 3) + j;
        size_t gin = ((size_t)(b << 10) + n) * DM + h * 64;
        size_t gout = ((size_t)(bh << 10) + n) * 88;
        {
            float v0 = gq[gin + lane], v1 = gq[gin + 32 + lane];
            float s = v0 * v0 + v1 * v1;
#pragma unroll
            for (int o = 16; o; o >>= 1) s += __shfl_xor_sync(0xffffffffu, s, o);
            float qt = sqrtf(s + 1.0f);
            bf16 h0 = __float2bfloat16(v0);
            g_qph[gout + lane] = h0;
            g_qpl[gout + lane] = __float2bfloat16(v0 - __bfloat162float(h0));
            bf16 h1 = __float2bfloat16(v1);
            g_qph[gout + 32 + lane] = h1;
            g_qpl[gout + 32 + lane] = __float2bfloat16(v1 - __bfloat162float(h1));
            if (lane < 24) {
                float pv = (lane == 0) ? qt : 0.f;
                bf16 ph = __float2bfloat16(pv);
                g_qph[gout + 64 + lane] = ph;
                g_qpl[gout + 64 + lane] = __float2bfloat16(pv - __bfloat162float(ph));
            }
        }
        {
            float v0 = gk[gin + lane], v1 = gk[gin + 32 + lane];
            float s = v0 * v0 + v1 * v1;
#pragma unroll
            for (int o = 16; o; o >>= 1) s += __shfl_xor_sync(0xffffffffu, s, o);
            float kt = -sqrtf(s + 1.0f);
            bf16 h0 = __float2bfloat16(v0);
            g_kph[gout + lane] = h0;
            g_kpl[gout + lane] = __float2bfloat16(v0 - __bfloat162float(h0));
            bf16 h1 = __float2bfloat16(v1);
            g_kph[gout + 32 + lane] = h1;
            g_kpl[gout + 32 + lane] = __float2bfloat16(v1 - __bfloat162float(h1));
            if (lane < 24) {
                float pv = (lane == 0) ? kt : 0.f;
                bf16 ph = __float2bfloat16(pv);
                g_kph[gout + 64 + lane] = ph;
                g_kpl[gout + 64 + lane] = __float2bfloat16(pv - __bfloat162float(ph));
            }
        }
        {
            int nl = (wid << 3) + j;
            float v0 = gv[gin + lane], v1 = gv[gin + 32 + lane];
            sv[nl][lane] = v0; sv[nl][32 + lane] = v1;
            float s = v0 * v0 + v1 * v1;
#pragma unroll
            for (int o = 16; o; o >>= 1) s += __shfl_xor_sync(0xffffffffu, s, o);
            if (lane == 0) svt[nl] = sqrtf(s + 1.0f);
        }
    }
    __syncthreads();
    for (int it = tid; it < 72 * 64; it += 256) {
        int c = it >> 6, nl = it & 63;
        float val = (c == 0) ? svt[nl] : ((c < 65) ? sv[nl][c - 1] : 0.f);
        bf16 hh = __float2bfloat16(val);
        size_t o = ((size_t)bh * 72 + c) * SEQ + n0 + nl;
        g_vTh[o] = hh;
        g_vTl[o] = __float2bfloat16(val - __bfloat162float(hh));
    }
}

// ---------------- flash attention (bf16 3-pass mma, fused softmax) -----------
#define QRB 176
#define VRB 144
#define FS_QH 0
#define FS_QL 11264
#define FS_KH 22528
#define FS_KL 33792
#define FS_VH 45056
#define FS_VL 55424
#define FSMEM 65792

__global__ __launch_bounds__(128)
void flash_attn() {
    extern __shared__ char smf[];
    uint32_t sb = smem_to_u32(smf);
    int bh = blockIdx.y, q0 = blockIdx.x * 64;
    int b = bh >> 4, h = bh & 15;
    int tid = threadIdx.x, lane = tid & 31, wid = tid >> 5;
    int g = lane >> 2, t4 = lane & 3;

    for (int i = tid; i < 704; i += 128) {
        int row = i / 11, seg = i - row * 11;
        size_t gsrc = ((size_t)(bh << 10) + q0 + row) * 88 + seg * 8;
        uint32_t sd = row * QRB + seg * 16;
        cp16(sb + FS_QH + sd, g_qph + gsrc);
        cp16(sb + FS_QL + sd, g_qpl + gsrc);
    }
    cp_commit();

    float acc_o[9][4];
#pragma unroll
    for (int nj = 0; nj < 9; nj++)
#pragma unroll
        for (int e = 0; e < 4; e++) acc_o[nj][e] = 0.f;
    float m_g = -1e30f, m_g8 = -1e30f;

    uint32_t qa_off = (uint32_t)((wid * 16 + (lane & 15)) * QRB + (lane >> 4) * 16);
    uint32_t kb_off = (uint32_t)((lane & 7) * QRB + ((lane >> 3) & 1) * 16);
    uint32_t vb_off = (uint32_t)((lane & 7) * VRB + ((lane >> 3) & 1) * 16);

    for (int kt = 0; kt < 16; kt++) {
        __syncthreads();
        int k0 = kt * 64;
        for (int i = tid; i < 704; i += 128) {
            int row = i / 11, seg = i - row * 11;
            size_t gsrc = ((size_t)(bh << 10) + k0 + row) * 88 + seg * 8;
            uint32_t sd = row * QRB + seg * 16;
            cp16(sb + FS_KH + sd, g_kph + gsrc);
            cp16(sb + FS_KL + sd, g_kpl + gsrc);
        }
        for (int i = tid; i < 648; i += 128) {
            int c = i / 9, seg = i - c * 9;
            size_t gsrc = ((size_t)bh * 72 + c) * SEQ + k0 + seg * 8;
            uint32_t sd = c * VRB + seg * 16;
            cp16(sb + FS_VH + sd, g_vTh + gsrc);
            cp16(sb + FS_VL + sd, g_vTl + gsrc);
        }
        cp_commit();
        asm volatile("cp.async.wait_group 0;" ::: "memory");
        __syncthreads();

        float s[8][4];
#pragma unroll
        for (int nj = 0; nj < 8; nj++)
#pragma unroll
            for (int e = 0; e < 4; e++) s[nj][e] = 0.f;
#pragma unroll
        for (int k16 = 0; k16 < 5; k16++) {
            uint32_t aH[4], aL[4];
            ldm_x4(aH, sb + FS_QH + qa_off + k16 * 32);
            ldm_x4(aL, sb + FS_QL + qa_off + k16 * 32);
#pragma unroll
            for (int nj = 0; nj < 8; nj++) {
                uint32_t bHf[2], bLf[2];
                uint32_t bd = kb_off + nj * (8 * QRB) + k16 * 32;
                ldm_x2(bHf, sb + FS_KH + bd);
                ldm_x2(bLf, sb + FS_KL + bd);
                mma_bf16(s[nj], aH, bHf);
                mma_bf16(s[nj], aH, bLf);
                mma_bf16(s[nj], aL, bHf);
            }
        }
        float mt_g = -1e30f, mt_g8 = -1e30f;
#pragma unroll
        for (int nj = 0; nj < 8; nj++) {
            s[nj][0] = fmaf(0.25f, s[nj][0], 0.25f);
            s[nj][1] = fmaf(0.25f, s[nj][1], 0.25f);
            s[nj][2] = fmaf(0.25f, s[nj][2], 0.25f);
            s[nj][3] = fmaf(0.25f, s[nj][3], 0.25f);
            mt_g  = fmaxf(mt_g,  fmaxf(s[nj][0], s[nj][1]));
            mt_g8 = fmaxf(mt_g8, fmaxf(s[nj][2], s[nj][3]));
        }
        mt_g  = fmaxf(mt_g,  __shfl_xor_sync(0xffffffffu, mt_g, 1));
        mt_g  = fmaxf(mt_g,  __shfl_xor_sync(0xffffffffu, mt_g, 2));
        mt_g8 = fmaxf(mt_g8, __shfl_xor_sync(0xffffffffu, mt_g8, 1));
        mt_g8 = fmaxf(mt_g8, __shfl_xor_sync(0xffffffffu, mt_g8, 2));
        float mn_g = fmaxf(m_g, mt_g), mn_g8 = fmaxf(m_g8, mt_g8);
        float sc_g = __expf(m_g - mn_g), sc_g8 = __expf(m_g8 - mn_g8);
        m_g = mn_g; m_g8 = mn_g8;
#pragma unroll
        for (int nj = 0; nj < 8; nj++) {
            s[nj][0] = __expf(s[nj][0] - mn_g);
            s[nj][1] = __expf(s[nj][1] - mn_g);
            s[nj][2] = __expf(s[nj][2] - mn_g8);
            s[nj][3] = __expf(s[nj][3] - mn_g8);
        }
#pragma unroll
        for (int nj = 0; nj < 9; nj++) {
            acc_o[nj][0] *= sc_g;  acc_o[nj][1] *= sc_g;
            acc_o[nj][2] *= sc_g8; acc_o[nj][3] *= sc_g8;
        }
#pragma unroll
        for (int k16 = 0; k16 < 4; k16++) {
            int u0 = 2 * k16, u1 = u0 + 1;
            uint32_t pH[4], pL[4];
            pH[0] = pack_bf2(s[u0][0], s[u0][1]);
            pH[1] = pack_bf2(s[u0][2], s[u0][3]);
            pH[2] = pack_bf2(s[u1][0], s[u1][1]);
            pH[3] = pack_bf2(s[u1][2], s[u1][3]);
            {
                __nv_bfloat162 t0 = *reinterpret_cast<__nv_bfloat162*>(&pH[0]);
                __nv_bfloat162 t1 = *reinterpret_cast<__nv_bfloat162*>(&pH[1]);
                __nv_bfloat162 t2 = *reinterpret_cast<__nv_bfloat162*>(&pH[2]);
                __nv_bfloat162 t3 = *reinterpret_cast<__nv_bfloat162*>(&pH[3]);
                pL[0] = pack_bf2(s[u0][0] - __bfloat162float(__low2bfloat16(t0)),
                                 s[u0][1] - __bfloat162float(__high2bfloat16(t0)));
                pL[1] = pack_bf2(s[u0][2] - __bfloat162float(__low2bfloat16(t1)),
                                 s[u0][3] - __bfloat162float(__high2bfloat16(t1)));
                pL[2] = pack_bf2(s[u1][0] - __bfloat162float(__low2bfloat16(t2)),
                                 s[u1][1] - __bfloat162float(__high2bfloat16(t2)));
                pL[3] = pack_bf2(s[u1][2] - __bfloat162float(__low2bfloat16(t3)),
                                 s[u1][3] - __bfloat162float(__high2bfloat16(t3)));
            }
#pragma unroll
            for (int nj = 0; nj < 9; nj++) {
                uint32_t bHf[2], bLf[2];
                uint32_t bd = vb_off + nj * (8 * VRB) + k16 * 32;
                ldm_x2(bHf, sb + FS_VH + bd);
                ldm_x2(bLf, sb + FS_VL + bd);
                mma_bf16(acc_o[nj], pH, bHf);
                mma_bf16(acc_o[nj], pH, bLf);
                mma_bf16(acc_o[nj], pL, bHf);
            }
        }
    }

    float d_g = 0.f, d_g8 = 0.f;
#pragma unroll
    for (int nj = 0; nj < 9; nj++) {
#pragma unroll
        for (int e = 0; e < 2; e++) {
            int c = nj * 8 + 2 * t4 + e;
            float o0 = acc_o[nj][e], o1 = acc_o[nj][e + 2];
            float sgn = (c == 0) ? 1.f : -1.f;
            d_g  += sgn * o0 * o0;
            d_g8 += sgn * o1 * o1;
        }
    }
    d_g  += __shfl_xor_sync(0xffffffffu, d_g, 1);
    d_g  += __shfl_xor_sync(0xffffffffu, d_g, 2);
    d_g8 += __shfl_xor_sync(0xffffffffu, d_g8, 1);
    d_g8 += __shfl_xor_sync(0xffffffffu, d_g8, 2);
    float inv_g  = rsqrtf(fmaxf(d_g,  1e-8f));
    float inv_g8 = rsqrtf(fmaxf(d_g8, 1e-8f));

    int n_g  = q0 + wid * 16 + g;
    size_t tok_g  = (size_t)(b << 10) + n_g;
    size_t o_g  = tok_g * 1088 + h * 65;
    size_t o_g8 = (tok_g + 8) * 1088 + h * 65;
#pragma unroll
    for (int nj = 0; nj < 9; nj++) {
#pragma unroll
        for (int e = 0; e < 2; e++) {
            int c = nj * 8 + 2 * t4 + e;
            if (c < 65) {
                float v0 = acc_o[nj][e] * inv_g;
                bf16 h0 = __float2bfloat16(v0);
                g_cath[o_g + c] = h0;
                g_catl[o_g + c] = __float2bfloat16(v0 - __bfloat162float(h0));
                float v1 = acc_o[nj][e + 2] * inv_g8;
                bf16 h1v = __float2bfloat16(v1);
                g_cath[o_g8 + c] = h1v;
                g_catl[o_g8 + c] = __float2bfloat16(v1 - __bfloat162float(h1v));
            }
        }
    }
}

// ---------------- Lorentz resnet ---------------------------------------------
__global__ __launch_bounds__(256)
void lresnet_kernel(const float* __restrict__ xin, const float* __restrict__ ysp,
                    const float* __restrict__ wp, float* __restrict__ out) {
    __shared__ float sm[32];
    int t = blockIdx.x, tid = threadIdx.x;
    const float* xr = xin + (size_t)t * DM;
    const float* yr = ysp + (size_t)t * 1023;
    float yv[4]; float ss = 0.f;
#pragma unroll
    for (int j = 0; j < 4; j++) {
        int d = tid + j * 256;
        if (d >= 1) { yv[j] = yr[d - 1]; ss += yv[j] * yv[j]; } else yv[j] = 0.f;
    }
    ss = block_sum(ss, sm);
    float w0 = *wp;
    float ytime = sqrtf(ss + 1.0f);
    float z[4]; float lin = 0.f;
#pragma unroll
    for (int j = 0; j < 4; j++) {
        int d = tid + j * 256;
        float y = (d == 0) ? ytime : yv[j];
        z[j] = xr[d] + w0 * y;
        lin += (d == 0) ? -z[j] * z[j] : z[j] * z[j];
    }
    lin = block_sum(lin, sm);
    float inv = rsqrtf(fmaxf(-lin, 1e-8f));
#pragma unroll
    for (int j = 0; j < 4; j++)
        out[(size_t)t * DM + tid + j * 256] = z[j] * inv;
}

// ---------------- exact GELU + time lift -> bf16 hi/lo ------------------------
__global__ __launch_bounds__(256)
void gelu_split() {
    __shared__ float sm[32];
    int t = blockIdx.x, tid = threadIdx.x;
    const float* r = g_hf + (size_t)t * DFF;
    bf16* oh = g_hfh + (size_t)t * DFF;
    bf16* ol = g_hfl + (size_t)t * DFF;
    float vals[16]; float s = 0.f;
#pragma unroll
    for (int j = 0; j < 16; j++) {
        int d = 1 + tid + j * 256;
        if (d < DFF) {
            float x = r[d];
            float gg = x * normcdff(x);
            vals[j] = gg;
            s += gg * gg;
        } else vals[j] = 0.f;
    }
    s = block_sum(s, sm);
#pragma unroll
    for (int j = 0; j < 16; j++) {
        int d = 1 + tid + j * 256;
        if (d < DFF) {
            bf16 h = __float2bfloat16(vals[j]);
            oh[d] = h;
            ol[d] = __float2bfloat16(vals[j] - __bfloat162float(h));
        }
    }
    if (tid == 0) {
        float tv = sqrtf(s + 1.f);
        bf16 h = __float2bfloat16(tv);
        oh[0] = h;
        ol[0] = __float2bfloat16(tv - __bfloat162float(h));
    }
}

// ---------------- launch ------------------------------------------------------
extern "C" void kernel_launch(void* const* d_in, const int* in_sizes, int n_in,
                              void* d_out, int out_size) {
    const float* x   = (const float*)d_in[0];
    const float* g1  = (const float*)d_in[1];
    const float* b1  = (const float*)d_in[2];
    const float* Wq  = (const float*)d_in[3];
    const float* bq  = (const float*)d_in[4];
    const float* Wk  = (const float*)d_in[5];
    const float* bk  = (const float*)d_in[6];
    const float* Wv  = (const float*)d_in[7];
    const float* bv  = (const float*)d_in[8];
    const float* Wo  = (const float*)d_in[9];
    const float* bo  = (const float*)d_in[10];
    const float* g2  = (const float*)d_in[11];
    const float* b2  = (const float*)d_in[12];
    const float* Wfc = (const float*)d_in[13];
    const float* bfc = (const float*)d_in[14];
    const float* Wpj = (const float*)d_in[15];
    const float* bpj = (const float*)d_in[16];
    const float* w1  = (const float*)d_in[17];
    const float* w2  = (const float*)d_in[18];
    float* out = (float*)d_out;

    cudaFuncSetAttribute(hgemm3, cudaFuncAttributeMaxDynamicSharedMemorySize, GSMEM);
    cudaFuncSetAttribute(flash_attn, cudaFuncAttributeMaxDynamicSharedMemorySize, FSMEM);

    float *p_qkv, *p_ax, *p_x2, *p_hf, *p_pj, *p_bqkv;
    bf16 *p_lxh, *p_lxl, *p_cath, *p_catl, *p_h1h, *p_h1l, *p_hfh, *p_hfl;
    bf16 *Wqkvh, *Wqkvl, *WoTh, *WoTl, *WfcTh, *WfcTl, *WpjTh, *WpjTl;
    cudaGetSymbolAddress((void**)&p_qkv, g_qkv);
    cudaGetSymbolAddress((void**)&p_ax,  g_ax);
    cudaGetSymbolAddress((void**)&p_x2,  g_x2);
    cudaGetSymbolAddress((void**)&p_hf,  g_hf);
    cudaGetSymbolAddress((void**)&p_pj,  g_pj);
    cudaGetSymbolAddress((void**)&p_bqkv, g_bqkv);
    cudaGetSymbolAddress((void**)&p_lxh, g_lxh);
    cudaGetSymbolAddress((void**)&p_lxl, g_lxl);
    cudaGetSymbolAddress((void**)&p_cath, g_cath);
    cudaGetSymbolAddress((void**)&p_catl, g_catl);
    cudaGetSymbolAddress((void**)&p_h1h, g_h1h);
    cudaGetSymbolAddress((void**)&p_h1l, g_h1l);
    cudaGetSymbolAddress((void**)&p_hfh, g_hfh);
    cudaGetSymbolAddress((void**)&p_hfl, g_hfl);
    cudaGetSymbolAddress((void**)&Wqkvh, g_Wqkvh);  cudaGetSymbolAddress((void**)&Wqkvl, g_Wqkvl);
    cudaGetSymbolAddress((void**)&WoTh, g_WoTh);    cudaGetSymbolAddress((void**)&WoTl, g_WoTl);
    cudaGetSymbolAddress((void**)&WfcTh, g_WfcTh);  cudaGetSymbolAddress((void**)&WfcTl, g_WfcTl);
    cudaGetSymbolAddress((void**)&WpjTh, g_WpjTh);  cudaGetSymbolAddress((void**)&WpjTl, g_WpjTl);

    // weight transpose + split (qkv into one concatenated array)
    wsplitT<<<dim3(32, 32), 256>>>(Wq,  Wqkvh,                      Wqkvl,                      1024, 1024, 1024, 1024);
    wsplitT<<<dim3(32, 32), 256>>>(Wk,  Wqkvh + (size_t)1024*1024,  Wqkvl + (size_t)1024*1024,  1024, 1024, 1024, 1024);
    wsplitT<<<dim3(32, 32), 256>>>(Wv,  Wqkvh + (size_t)2048*1024,  Wqkvl + (size_t)2048*1024,  1024, 1024, 1024, 1024);
    wsplitT<<<dim3(32, 33), 256>>>(Wo,  WoTh,  WoTl,  1040, 1023, 1088, 1024);
    wsplitT<<<dim3(128, 32), 256>>>(Wfc, WfcTh, WfcTl, 1024, 4095, 1024, 4096);
    wsplitT<<<dim3(32, 128), 256>>>(Wpj, WpjTh, WpjTl, 4096, 1023, 4096, 1024);
    biascat<<<12, 256>>>(bq, bk, bv);

    // 1. lx = lorentz_layernorm(x) -> bf16 split
    lnorm_split<<<TOK, 256>>>(x, g1, b1, p_lxh, p_lxl);
    // 2. fused QKV projection (one 768-CTA GEMM)
    hgemm3<<<dim3(24, 32), 256, GSMEM>>>(p_lxh, p_lxl, Wqkvh, Wqkvl, p_bqkv, p_qkv, 1024, 3072, 0, 0, 1);
    // 3. build padded/split attention operands
    qkv_prep<<<dim3(16, BH), 256>>>();
    // 4. fused flash attention -> cat (bf16 hi/lo)
    flash_attn<<<dim3(16, BH), 128, FSMEM>>>();
    // 5. output projection + first lorentz resnet
    hgemm3<<<dim3(8, 32), 256, GSMEM>>>(p_cath, p_catl, WoTh, WoTl, bo, p_ax, 1088, 1023, 1023, 0, 0);
    lresnet_kernel<<<TOK, 256>>>(x, p_ax, w1, p_x2);
    // 6. MLP branch
    lnorm_split<<<TOK, 256>>>(p_x2, g2, b2, p_h1h, p_h1l);
    hgemm3<<<dim3(32, 32), 256, GSMEM>>>(p_h1h, p_h1l, WfcTh, WfcTl, bfc, p_hf, 1024, 4095, DFF, 1, 0);
    gelu_split<<<TOK, 256>>>();
    hgemm3<<<dim3(8, 32), 256, GSMEM>>>(p_hfh, p_hfl, WpjTh, WpjTl, bpj, p_pj, 4096, 1023, 1023, 0, 0);
    // 7. final lorentz resnet -> output
    lresnet_kernel<<<TOK, 256>>>(p_x2, p_pj, w2, out);
}